// round 7
// baseline (speedup 1.0000x reference)
#include <cuda_runtime.h>
#include <cuda_bf16.h>
#include <math.h>
#include <stdint.h>

// ---------------- problem constants ----------------
#define BATCH  2
#define LSEQ   8192
#define DMODEL 1024
#define NPROJ  6176    // 2*D_INNER + 2*NQK*DSTATE + NV
#define CONVD  5120    // D_INNER + 2*NQK*DSTATE
#define DINNER 1024
#define NH     32
#define DST    64
#define HDIM   32
#define CHK    128
#define NCH    64
#define MROWS  (BATCH*LSEQ)   // 16384

// split-bf16 GEMM constants
#define K3     3072            // 3 * 1024
#define BM     256
#define BN     128
#define BK     64              // 64 bf16 = 128B = one swizzle atom row
#define NSTAGE 3
#define NCHUNK (K3/BK)         // 48
#define NPROJ_PAD 6400

// ---------------- scratch (device globals) --------
__device__ float g_xbcza[(size_t)MROWS * NPROJ];
__device__ float g_conv [(size_t)MROWS * CONVD];
__device__ float g_acum [(size_t)MROWS * NH];
__device__ float g_y    [(size_t)MROWS * DINNER];   // Y_diag
__device__ float g_states[(size_t)BATCH*NCH*NH*HDIM*DST];
__device__ float g_prevs [(size_t)BATCH*NCH*NH*HDIM*DST];
__device__ float g_dc   [BATCH*NCH*NH];

__device__ __nv_bfloat16 g_uS   [(size_t)MROWS * K3];
__device__ __nv_bfloat16 g_WinS [(size_t)NPROJ_PAD * K3];
__device__ __nv_bfloat16 g_yS   [(size_t)MROWS * K3];
__device__ __nv_bfloat16 g_WoutS[(size_t)1024 * K3];

// ---------------- helpers ----------------
__device__ __forceinline__ uint32_t smem_u32(const void* p) {
    uint32_t a;
    asm("{ .reg .u64 t; cvta.to.shared.u64 t, %1; cvt.u32.u64 %0, t; }"
        : "=r"(a) : "l"(p));
    return a;
}
#define SW128(o) ((o) ^ (((o) >> 3) & 0x70))

__device__ __forceinline__ void ldsm4(uint32_t* r, uint32_t addr) {
    asm volatile("ldmatrix.sync.aligned.m8n8.x4.shared.b16 {%0,%1,%2,%3}, [%4];"
        : "=r"(r[0]), "=r"(r[1]), "=r"(r[2]), "=r"(r[3]) : "r"(addr));
}
__device__ __forceinline__ void mma16816(float* c, const uint32_t* a,
                                         uint32_t b0, uint32_t b1) {
    asm volatile(
        "mma.sync.aligned.m16n8k16.row.col.f32.bf16.bf16.f32 "
        "{%0,%1,%2,%3}, {%4,%5,%6,%7}, {%8,%9}, {%0,%1,%2,%3};"
        : "+f"(c[0]), "+f"(c[1]), "+f"(c[2]), "+f"(c[3])
        : "r"(a[0]), "r"(a[1]), "r"(a[2]), "r"(a[3]), "r"(b0), "r"(b1));
}

// ============================================================
// split kernels (vectorized): fp32 [M,1024] -> bf16 [M,3072]
// A-variant: [hi | lo | hi] ; B-variant: [hi | hi | lo]
// ============================================================
__global__ __launch_bounds__(256)
void split3_Av(const float* __restrict__ X, __nv_bfloat16* __restrict__ Y)
{
    size_t idx = (size_t)blockIdx.x * 256 + threadIdx.x;  // over M*512
    size_t m = idx >> 9;
    int k2 = (int)(idx & 511) * 2;
    float2 x = *(const float2*)&X[m * 1024 + k2];
    __nv_bfloat16 h0 = __float2bfloat16(x.x);
    __nv_bfloat16 h1 = __float2bfloat16(x.y);
    __nv_bfloat16 l0 = __float2bfloat16(x.x - __bfloat162float(h0));
    __nv_bfloat16 l1 = __float2bfloat16(x.y - __bfloat162float(h1));
    __nv_bfloat162 hi; hi.x = h0; hi.y = h1;
    __nv_bfloat162 lo; lo.x = l0; lo.y = l1;
    __nv_bfloat16* row = Y + m * (size_t)K3;
    *(__nv_bfloat162*)&row[k2]        = hi;
    *(__nv_bfloat162*)&row[1024 + k2] = lo;
    *(__nv_bfloat162*)&row[2048 + k2] = hi;
}
__global__ __launch_bounds__(256)
void split3_Bv(const float* __restrict__ X, __nv_bfloat16* __restrict__ Y)
{
    size_t idx = (size_t)blockIdx.x * 256 + threadIdx.x;
    size_t m = idx >> 9;
    int k2 = (int)(idx & 511) * 2;
    float2 x = *(const float2*)&X[m * 1024 + k2];
    __nv_bfloat16 h0 = __float2bfloat16(x.x);
    __nv_bfloat16 h1 = __float2bfloat16(x.y);
    __nv_bfloat16 l0 = __float2bfloat16(x.x - __bfloat162float(h0));
    __nv_bfloat16 l1 = __float2bfloat16(x.y - __bfloat162float(h1));
    __nv_bfloat162 hi; hi.x = h0; hi.y = h1;
    __nv_bfloat162 lo; lo.x = l0; lo.y = l1;
    __nv_bfloat16* row = Y + m * (size_t)K3;
    *(__nv_bfloat162*)&row[k2]        = hi;
    *(__nv_bfloat162*)&row[1024 + k2] = hi;
    *(__nv_bfloat162*)&row[2048 + k2] = lo;
}

// ============================================================
// bf16 warp-MMA GEMM: C[M, ldc](fp32) = A'[M,K3] @ B'[*,K3]^T
// BM=256, BN=128, BK=64, 512 threads (16 warps, 4x4; warp tile 64x32),
// 3-stage cp.async.
// ============================================================
__global__ __launch_bounds__(512, 1)
void gemm_mma(float* __restrict__ C,
              const __nv_bfloat16* __restrict__ A,
              const __nv_bfloat16* __restrict__ B,
              int N_out, int ldc)
{
    extern __shared__ char smem[];
    const int tid  = threadIdx.x;
    const int wid  = tid >> 5;
    const int lane = tid & 31;
    const int m0 = blockIdx.y * BM;
    const int n0 = blockIdx.x * BN;
    const int wm = (wid >> 2) * 64;   // 0,64,128,192
    const int wn = (wid & 3) * 32;    // 0,32,64,96

    // per-stage: A tile 256x128B (32KB) + B tile 128x128B (16KB) = 48KB
    char* tiles = smem;

    auto fill = [&](int chunk) {
        int s = chunk % NSTAGE;
        char* As = tiles + s * 49152;
        char* Bs = As + 32768;
        const char* Ag = (const char*)(A + (size_t)m0 * K3 + chunk * BK);
        const char* Bg = (const char*)(B + (size_t)n0 * K3 + chunk * BK);
        uint32_t Asb = smem_u32(As), Bsb = smem_u32(Bs);
#pragma unroll
        for (int r = 0; r < 4; r++) {                 // A: 2048 16B-chunks
            int cid = tid + r * 512;
            int row = cid >> 3, col = cid & 7;
            uint32_t dst = Asb + SW128(row * 128 + col * 16);
            const void* src = Ag + (size_t)row * (K3 * 2) + col * 16;
            asm volatile("cp.async.cg.shared.global [%0], [%1], 16;" :: "r"(dst), "l"(src));
        }
#pragma unroll
        for (int r = 0; r < 2; r++) {                 // B: 1024 16B-chunks
            int cid = tid + r * 512;
            int row = cid >> 3, col = cid & 7;
            uint32_t dst = Bsb + SW128(row * 128 + col * 16);
            const void* src = Bg + (size_t)row * (K3 * 2) + col * 16;
            asm volatile("cp.async.cg.shared.global [%0], [%1], 16;" :: "r"(dst), "l"(src));
        }
        asm volatile("cp.async.commit_group;" ::: "memory");
    };

    float acc[4][4][4];
#pragma unroll
    for (int mi = 0; mi < 4; mi++)
#pragma unroll
        for (int ni = 0; ni < 4; ni++)
#pragma unroll
            for (int r = 0; r < 4; r++) acc[mi][ni][r] = 0.f;

    fill(0); fill(1);

    const int lrow = lane & 15;
    const int lcol = lane >> 4;

    for (int i = 0; i < NCHUNK; i++) {
        int s = i % NSTAGE;
        if (i + 1 < NCHUNK)
            asm volatile("cp.async.wait_group 1;" ::: "memory");
        else
            asm volatile("cp.async.wait_group 0;" ::: "memory");
        __syncthreads();

        if (i + 2 < NCHUNK) fill(i + 2);

        uint32_t Asb = smem_u32(tiles + s * 49152);
        uint32_t Bsb = Asb + 32768;

#pragma unroll
        for (int ks = 0; ks < 4; ks++) {
            uint32_t a[4][4], b[2][4];
#pragma unroll
            for (int mi = 0; mi < 4; mi++) {
                int row = wm + mi * 16 + lrow;
                ldsm4(a[mi], Asb + SW128(row * 128 + (ks * 2 + lcol) * 16));
            }
#pragma unroll
            for (int bi = 0; bi < 2; bi++) {
                int row = wn + bi * 16 + lrow;
                ldsm4(b[bi], Bsb + SW128(row * 128 + (ks * 2 + lcol) * 16));
            }
#pragma unroll
            for (int mi = 0; mi < 4; mi++)
#pragma unroll
                for (int ni = 0; ni < 4; ni++) {
                    int bi = ni >> 1, hf = ni & 1;
                    mma16816(acc[mi][ni], a[mi], b[bi][hf], b[bi][2 + hf]);
                }
        }
    }

    // epilogue
    const int gr = lane >> 2;
    const int gc = (lane & 3) * 2;
#pragma unroll
    for (int mi = 0; mi < 4; mi++) {
        int m = m0 + wm + mi * 16 + gr;
#pragma unroll
        for (int ni = 0; ni < 4; ni++) {
            int n = n0 + wn + ni * 8 + gc;
            if (n < N_out) {
                float2 v0 = make_float2(acc[mi][ni][0], acc[mi][ni][1]);
                float2 v1 = make_float2(acc[mi][ni][2], acc[mi][ni][3]);
                *(float2*)&C[(size_t)m * ldc + n]       = v0;
                *(float2*)&C[(size_t)(m + 8) * ldc + n] = v1;
            }
        }
    }
}

// ============================================================
// depthwise causal conv (DCONV=4) + bias — register-blocked:
// each thread: 4 channels (float4) x 4 timesteps.
// ============================================================
__global__ __launch_bounds__(256)
void conv_kernel(const float* __restrict__ cw, const float* __restrict__ cb)
{
    int c4 = blockIdx.x * 256 + threadIdx.x;   // 0..1279
    int ch = c4 * 4;
    int m0 = blockIdx.y * 4;
    int t0 = m0 & (LSEQ - 1);

    const float4* wp = (const float4*)(cw + ch * 4);
    float4 w0 = wp[0], w1 = wp[1], w2 = wp[2], w3 = wp[3];
    float4 bias = *(const float4*)(cb + ch);

    float4 r[7];
    const float* base = g_xbcza + (size_t)m0 * NPROJ + ch;
#pragma unroll
    for (int k = 0; k < 7; k++) {
        int tt = t0 - 3 + k;
        if (tt >= 0)
            r[k] = *(const float4*)(base + (long)(k - 3) * NPROJ);
        else
            r[k] = make_float4(0.f, 0.f, 0.f, 0.f);
    }

    float* outbase = g_conv + (size_t)m0 * CONVD + ch;
#pragma unroll
    for (int j = 0; j < 4; j++) {
        float4 o = bias;
        o.x += w0.x * r[j].x + w0.y * r[j+1].x + w0.z * r[j+2].x + w0.w * r[j+3].x;
        o.y += w1.x * r[j].y + w1.y * r[j+1].y + w1.z * r[j+2].y + w1.w * r[j+3].y;
        o.z += w2.x * r[j].z + w2.y * r[j+1].z + w2.z * r[j+2].z + w2.w * r[j+3].z;
        o.w += w3.x * r[j].w + w3.y * r[j+1].w + w3.z * r[j+2].w + w3.w * r[j+3].w;
        *(float4*)(outbase + (size_t)j * CONVD) = o;
    }
}

// ============================================================
// per-(b,chunk,head) SSD chunk kernel
// ============================================================
__global__ __launch_bounds__(256)
void chunk_kernel()
{
    extern __shared__ float sm[];
    float* CsT = sm;               // [64][132]
    float* BsT = sm + 8448;        // [64][132]
    float* Xs  = sm + 16896;       // [128][36]
    float* MsT = sm + 21504;       // [128][132]
    float* sA  = sm + 38400;       // [128]
    float* sDs = sm + 38528;       // [128]

    const int tid = threadIdx.x;
    const int bid = blockIdx.x;
    const int h = bid & 31;
    const int c = (bid >> 5) & 63;
    const int b = bid >> 11;
    const size_t m0 = (size_t)b * LSEQ + (size_t)c * CHK;

    {
        int n = tid & 63, lb = tid >> 6;
        for (int l = lb; l < CHK; l += 4) {
            const float* row = &g_conv[(m0 + l) * CONVD];
            BsT[n * 132 + l] = row[DINNER + h * DST + n];
            CsT[n * 132 + l] = row[DINNER + NH * DST + h * DST + n];
        }
        int p = tid & 31, lb2 = tid >> 5;
        for (int l = lb2; l < CHK; l += 8)
            Xs[l * 36 + p] = g_conv[(m0 + l) * CONVD + h * HDIM + p];
    }

    if (tid < CHK) {
        float alog = g_xbcza[(m0 + tid) * NPROJ + (CONVD + DINNER) + h];
        float dt = alog > 20.f ? alog : log1pf(expf(alog));
        sA[tid] = dt;
    }
    __syncthreads();
    for (int off = 1; off < CHK; off <<= 1) {
        float v = 0.f;
        if (tid < CHK && tid >= off) v = sA[tid - off];
        __syncthreads();
        if (tid < CHK) sA[tid] += v;
        __syncthreads();
    }
    if (tid < CHK) sA[tid] = -sA[tid];
    __syncthreads();
    float aLast = sA[CHK - 1];
    if (tid < CHK) {
        sDs[tid] = __expf(aLast - sA[tid]);
        g_acum[(m0 + tid) * NH + h] = sA[tid];
    }
    if (tid == 0) g_dc[(b * NCH + c) * NH + h] = __expf(aLast);
    __syncthreads();

    const int txp = tid & 15, typ = tid >> 4;
    const int l0 = typ * 8, s0 = txp * 8;
    if (typ < txp) {
#pragma unroll
        for (int j = 0; j < 8; j++)
#pragma unroll
            for (int i = 0; i < 8; i++)
                MsT[(s0 + j) * 132 + l0 + i] = 0.f;
    } else {
        float acc[8][8];
#pragma unroll
        for (int i = 0; i < 8; i++)
#pragma unroll
            for (int j = 0; j < 8; j++) acc[i][j] = 0.f;

        for (int n = 0; n < DST; n++) {
            float a[8], bb[8];
            float4 t0 = *(float4*)&CsT[n * 132 + l0];
            float4 t1 = *(float4*)&CsT[n * 132 + l0 + 4];
            float4 u0 = *(float4*)&BsT[n * 132 + s0];
            float4 u1 = *(float4*)&BsT[n * 132 + s0 + 4];
            a[0]=t0.x; a[1]=t0.y; a[2]=t0.z; a[3]=t0.w;
            a[4]=t1.x; a[5]=t1.y; a[6]=t1.z; a[7]=t1.w;
            bb[0]=u0.x; bb[1]=u0.y; bb[2]=u0.z; bb[3]=u0.w;
            bb[4]=u1.x; bb[5]=u1.y; bb[6]=u1.z; bb[7]=u1.w;
#pragma unroll
            for (int i = 0; i < 8; i++)
#pragma unroll
                for (int j = 0; j < 8; j++)
                    acc[i][j] += a[i] * bb[j];
        }
        float as0 = sA[s0];
        float el[8], es[8];
#pragma unroll
        for (int i = 0; i < 8; i++) el[i] = __expf(sA[l0 + i] - as0);
#pragma unroll
        for (int j = 0; j < 8; j++) es[j] = __expf(as0 - sA[s0 + j]);
#pragma unroll
        for (int j = 0; j < 8; j++)
#pragma unroll
            for (int i = 0; i < 8; i++) {
                float v = acc[i][j] * el[i] * es[j];
                if (typ == txp && i < j) v = 0.f;
                MsT[(s0 + j) * 132 + l0 + i] = v;
            }
    }
    __syncthreads();

    {
        const int p = tid & 31, lg = tid >> 5;
        const int lb = lg * 16;
        float yacc[16];
#pragma unroll
        for (int i = 0; i < 16; i++) yacc[i] = 0.f;
        for (int s = 0; s < CHK; s++) {
            float xv = Xs[s * 36 + p];
#pragma unroll
            for (int q = 0; q < 4; q++) {
                float4 mm = *(float4*)&MsT[s * 132 + lb + q * 4];
                yacc[q*4+0] += mm.x * xv;
                yacc[q*4+1] += mm.y * xv;
                yacc[q*4+2] += mm.z * xv;
                yacc[q*4+3] += mm.w * xv;
            }
        }
#pragma unroll
        for (int i = 0; i < 16; i++)
            g_y[(m0 + lb + i) * DINNER + h * HDIM + p] = yacc[i];
    }

    {
        const int n = tid & 63, pg = tid >> 6;
        float st[8];
#pragma unroll
        for (int i = 0; i < 8; i++) st[i] = 0.f;
        for (int s = 0; s < CHK; s++) {
            float w = BsT[n * 132 + s] * sDs[s];
            float4 x0 = *(float4*)&Xs[s * 36 + pg * 8];
            float4 x1 = *(float4*)&Xs[s * 36 + pg * 8 + 4];
            st[0] += w * x0.x; st[1] += w * x0.y; st[2] += w * x0.z; st[3] += w * x0.w;
            st[4] += w * x1.x; st[5] += w * x1.y; st[6] += w * x1.z; st[7] += w * x1.w;
        }
        size_t sb = ((size_t)((b * NCH + c) * NH + h)) * (HDIM * DST);
#pragma unroll
        for (int i = 0; i < 8; i++)
            g_states[sb + (pg * 8 + i) * DST + n] = st[i];
    }
}

// ============================================================
// inter-chunk state scan
// ============================================================
__global__ __launch_bounds__(512)
void scan_kernel()
{
    int b = blockIdx.x >> 5, h = blockIdx.x & 31;
    int tid = threadIdx.x;
    float4 S = make_float4(0.f, 0.f, 0.f, 0.f);
    for (int c = 0; c < NCH; c++) {
        size_t base = ((size_t)((b * NCH + c) * NH + h)) * (HDIM * DST);
        float4 stv = *(const float4*)&g_states[base + tid * 4];
        *(float4*)&g_prevs[base + tid * 4] = S;
        float d = g_dc[(b * NCH + c) * NH + h];
        S.x = S.x * d + stv.x;
        S.y = S.y * d + stv.y;
        S.z = S.z * d + stv.z;
        S.w = S.w * d + stv.w;
    }
}

// ============================================================
// Y_off + D*x skip + SiLU gating, fused bf16 split output -> g_yS
// ============================================================
__global__ __launch_bounds__(256)
void yoff_kernel(const float* __restrict__ Dvec, const float* __restrict__ z_bias)
{
    extern __shared__ float sm[];
    float* Cs = sm;            // [128][68]
    float* Pv = sm + 128*68;   // [32][68]
    float* eA = sm + 128*68 + 32*68;  // [128]

    const int tid = threadIdx.x;
    const int bid = blockIdx.x;
    const int h = bid & 31;
    const int c = (bid >> 5) & 63;
    const int b = bid >> 11;
    const size_t m0 = (size_t)b * LSEQ + (size_t)c * CHK;
    const size_t pbase = ((size_t)((b * NCH + c) * NH + h)) * (HDIM * DST);

    for (int i = tid; i < CHK * DST; i += 256) {
        int l = i >> 6, n = i & 63;
        Cs[l * 68 + n] = g_conv[(m0 + l) * CONVD + DINNER + NH * DST + h * DST + n];
    }
    for (int i = tid; i < HDIM * DST; i += 256) {
        int p = i >> 6, n = i & 63;
        Pv[p * 68 + n] = g_prevs[pbase + i];
    }
    if (tid < CHK)
        eA[tid] = __expf(g_acum[(m0 + tid) * NH + h]);
    __syncthreads();

    const int p = tid & 31, lg = tid >> 5;
    float4 vp[16];
#pragma unroll
    for (int q = 0; q < 16; q++)
        vp[q] = *(float4*)&Pv[p * 68 + q * 4];
    const float Dh = Dvec[h];
    const int col = h * HDIM + p;
    const float zb = z_bias[col];

#pragma unroll 4
    for (int li = 0; li < 16; li++) {
        int l = lg * 16 + li;
        float acc = 0.f;
#pragma unroll
        for (int q = 0; q < 16; q++) {
            float4 c4 = *(float4*)&Cs[l * 68 + q * 4];
            acc += c4.x * vp[q].x + c4.y * vp[q].y + c4.z * vp[q].z + c4.w * vp[q].w;
        }
        size_t mr = m0 + l;
        float xv = g_conv[mr * CONVD + h * HDIM + p];
        float yv = g_y[mr * DINNER + col] + eA[l] * acc + Dh * xv;
        float zz = g_xbcza[mr * NPROJ + CONVD + col] + zb;
        float sg = 1.f / (1.f + __expf(-zz));
        float gv = yv * (zz * sg);
        __nv_bfloat16 hi = __float2bfloat16(gv);
        __nv_bfloat16 lo = __float2bfloat16(gv - __bfloat162float(hi));
        __nv_bfloat16* yr = g_yS + mr * (size_t)K3;
        yr[col] = hi; yr[1024 + col] = lo; yr[2048 + col] = hi;
    }
}

// ============================================================
// launch
// ============================================================
extern "C" void kernel_launch(void* const* d_in, const int* in_sizes, int n_in,
                              void* d_out, int out_size)
{
    (void)in_sizes; (void)n_in; (void)out_size;
    const float* u      = (const float*)d_in[0];
    const float* W_in   = (const float*)d_in[1];
    const float* conv_w = (const float*)d_in[2];
    const float* conv_b = (const float*)d_in[3];
    const float* z_bias = (const float*)d_in[4];
    const float* Dv     = (const float*)d_in[5];
    const float* W_out  = (const float*)d_in[6];
    float* out = (float*)d_out;

    float *p_xbcza = nullptr;
    __nv_bfloat16 *p_uS = nullptr, *p_WinS = nullptr, *p_yS = nullptr, *p_WoutS = nullptr;
    cudaGetSymbolAddress((void**)&p_xbcza, g_xbcza);
    cudaGetSymbolAddress((void**)&p_uS, g_uS);
    cudaGetSymbolAddress((void**)&p_WinS, g_WinS);
    cudaGetSymbolAddress((void**)&p_yS, g_yS);
    cudaGetSymbolAddress((void**)&p_WoutS, g_WoutS);

    static const size_t GEMM_SMEM = NSTAGE * 49152;  // 144 KB
    cudaFuncSetAttribute(gemm_mma, cudaFuncAttributeMaxDynamicSharedMemorySize, (int)GEMM_SMEM);
    cudaFuncSetAttribute(chunk_kernel, cudaFuncAttributeMaxDynamicSharedMemorySize, 155 * 1024);
    cudaFuncSetAttribute(yoff_kernel,  cudaFuncAttributeMaxDynamicSharedMemorySize, 48 * 1024);

    // 0) splits for GEMM1
    split3_Av<<<MROWS * 2, 256>>>(u, p_uS);
    split3_Bv<<<NPROJ * 2, 256>>>(W_in, p_WinS);

    // 1) in-proj GEMM: xBCzA[M, 6176]
    {
        dim3 grid((NPROJ + BN - 1) / BN, MROWS / BM);   // (49, 64)
        gemm_mma<<<grid, 512, GEMM_SMEM>>>(p_xbcza, p_uS, p_WinS, NPROJ, NPROJ);
    }
    // 2) causal depthwise conv (register-blocked 4ch x 4t)
    {
        dim3 grid(CONVD / 1024, MROWS / 4);   // (5, 4096)
        conv_kernel<<<grid, 256>>>(conv_w, conv_b);
    }
    // 3) per-chunk SSD
    {
        size_t smem = 38656 * sizeof(float);
        chunk_kernel<<<BATCH * NCH * NH, 256, smem>>>();
    }
    // 4) inter-chunk scan
    scan_kernel<<<BATCH * NH, 512>>>();
    // 5) Y_off + skip + gate (writes bf16 split directly)
    {
        size_t smem = (128 * 68 + 32 * 68 + 128) * sizeof(float);
        yoff_kernel<<<BATCH * NCH * NH, 256, smem>>>(Dv, z_bias);
    }
    // 6) out-proj GEMM
    split3_Bv<<<1024 * 2, 256>>>(W_out, p_WoutS);
    {
        dim3 grid(1024 / BN, MROWS / BM);               // (8, 64)
        gemm_mma<<<grid, 512, GEMM_SMEM>>>(out, p_yS, p_WoutS, 1024, 1024);
    }
}

// round 8
// speedup vs baseline: 1.0461x; 1.0461x over previous
#include <cuda_runtime.h>
#include <cuda_bf16.h>
#include <math.h>
#include <stdint.h>

// ---------------- problem constants ----------------
#define BATCH  2
#define LSEQ   8192
#define DMODEL 1024
#define NPROJ  6176    // 2*D_INNER + 2*NQK*DSTATE + NV
#define CONVD  5120    // D_INNER + 2*NQK*DSTATE
#define DINNER 1024
#define NH     32
#define DST    64
#define HDIM   32
#define CHK    128
#define NCH    64
#define MROWS  (BATCH*LSEQ)   // 16384

// split-bf16 GEMM constants
#define K2     2048            // stored: [hi | lo]
#define BM     128
#define BN     128
#define BK     64              // 64 bf16 = 128B = one swizzle atom row
#define NSTAGE 3
#define NCHUNK 48              // logical K = 3072 (hi.hi + lo.hi + hi.lo)
#define NPROJ_PAD 6400

// ---------------- scratch (device globals) --------
__device__ float g_xbcza[(size_t)MROWS * NPROJ];
__device__ float g_conv [(size_t)MROWS * CONVD];
__device__ float g_acum [(size_t)MROWS * NH];
__device__ float g_y    [(size_t)MROWS * DINNER];   // Y_diag
__device__ float g_states[(size_t)BATCH*NCH*NH*HDIM*DST];
__device__ float g_prevs [(size_t)BATCH*NCH*NH*HDIM*DST];
__device__ float g_dc   [BATCH*NCH*NH];

__device__ __nv_bfloat16 g_uS   [(size_t)MROWS * K2];
__device__ __nv_bfloat16 g_WinS [(size_t)NPROJ_PAD * K2];
__device__ __nv_bfloat16 g_yS   [(size_t)MROWS * K2];
__device__ __nv_bfloat16 g_WoutS[(size_t)1024 * K2];

// ---------------- helpers ----------------
__device__ __forceinline__ uint32_t smem_u32(const void* p) {
    uint32_t a;
    asm("{ .reg .u64 t; cvta.to.shared.u64 t, %1; cvt.u32.u64 %0, t; }"
        : "=r"(a) : "l"(p));
    return a;
}
#define SW128(o) ((o) ^ (((o) >> 3) & 0x70))

__device__ __forceinline__ void ldsm4(uint32_t* r, uint32_t addr) {
    asm volatile("ldmatrix.sync.aligned.m8n8.x4.shared.b16 {%0,%1,%2,%3}, [%4];"
        : "=r"(r[0]), "=r"(r[1]), "=r"(r[2]), "=r"(r[3]) : "r"(addr));
}
__device__ __forceinline__ void mma16816(float* c, const uint32_t* a,
                                         uint32_t b0, uint32_t b1) {
    asm volatile(
        "mma.sync.aligned.m16n8k16.row.col.f32.bf16.bf16.f32 "
        "{%0,%1,%2,%3}, {%4,%5,%6,%7}, {%8,%9}, {%0,%1,%2,%3};"
        : "+f"(c[0]), "+f"(c[1]), "+f"(c[2]), "+f"(c[3])
        : "r"(a[0]), "r"(a[1]), "r"(a[2]), "r"(a[3]), "r"(b0), "r"(b1));
}

// ============================================================
// split kernel (vectorized): fp32 [M,1024] -> bf16 [M,2048] as [hi|lo]
// (the 3-term ordering lives in the GEMM's chunk->offset map)
// ============================================================
__global__ __launch_bounds__(256)
void split2(const float* __restrict__ X, __nv_bfloat16* __restrict__ Y)
{
    size_t idx = (size_t)blockIdx.x * 256 + threadIdx.x;  // over M*512
    size_t m = idx >> 9;
    int k2 = (int)(idx & 511) * 2;
    float2 x = *(const float2*)&X[m * 1024 + k2];
    __nv_bfloat16 h0 = __float2bfloat16(x.x);
    __nv_bfloat16 h1 = __float2bfloat16(x.y);
    __nv_bfloat16 l0 = __float2bfloat16(x.x - __bfloat162float(h0));
    __nv_bfloat16 l1 = __float2bfloat16(x.y - __bfloat162float(h1));
    __nv_bfloat162 hi; hi.x = h0; hi.y = h1;
    __nv_bfloat162 lo; lo.x = l0; lo.y = l1;
    __nv_bfloat16* row = Y + m * (size_t)K2;
    *(__nv_bfloat162*)&row[k2]        = hi;
    *(__nv_bfloat162*)&row[1024 + k2] = lo;
}

// ============================================================
// bf16 warp-MMA GEMM: C[M, ldc](fp32) = sum over 48 logical K-chunks:
// A part order [hi|lo|hi], B part order [hi|hi|lo].
// BM=128, BN=128, BK=64, 256 threads (8 warps 2x4), 3-stage cp.async,
// 2 CTAs/SM, k-fragment double buffering.
// ============================================================
__global__ __launch_bounds__(256, 2)
void gemm_mma(float* __restrict__ C,
              const __nv_bfloat16* __restrict__ A,
              const __nv_bfloat16* __restrict__ B,
              int N_out, int ldc)
{
    extern __shared__ char smem[];
    const int tid  = threadIdx.x;
    const int wid  = tid >> 5;
    const int lane = tid & 31;
    const int m0 = blockIdx.y * BM;
    const int n0 = blockIdx.x * BN;
    const int wm = (wid >> 2) * 64;   // 0 or 64
    const int wn = (wid & 3) * 32;    // 0,32,64,96

    char* tiles = smem;   // per-stage: A 16KB + B 16KB

    auto fill = [&](int chunk) {
        int s = chunk % NSTAGE;
        int part = chunk >> 4;                 // 0,1,2
        int ko = (chunk & 15) * BK;
        int aoff = (part == 1) ? 1024 : 0;     // A: [hi|lo|hi]
        int boff = (part == 2) ? 1024 : 0;     // B: [hi|hi|lo]
        char* As = tiles + s * 32768;
        char* Bs = As + 16384;
        const char* Ag = (const char*)(A + (size_t)m0 * K2 + aoff + ko);
        const char* Bg = (const char*)(B + (size_t)n0 * K2 + boff + ko);
        uint32_t Asb = smem_u32(As), Bsb = smem_u32(Bs);
#pragma unroll
        for (int r = 0; r < 4; r++) {
            int cid = tid + r * 256;
            int row = cid >> 3, col = cid & 7;
            uint32_t dst = Asb + SW128(row * 128 + col * 16);
            const void* src = Ag + (size_t)row * (K2 * 2) + col * 16;
            asm volatile("cp.async.cg.shared.global [%0], [%1], 16;" :: "r"(dst), "l"(src));
        }
#pragma unroll
        for (int r = 0; r < 4; r++) {
            int cid = tid + r * 256;
            int row = cid >> 3, col = cid & 7;
            uint32_t dst = Bsb + SW128(row * 128 + col * 16);
            const void* src = Bg + (size_t)row * (K2 * 2) + col * 16;
            asm volatile("cp.async.cg.shared.global [%0], [%1], 16;" :: "r"(dst), "l"(src));
        }
        asm volatile("cp.async.commit_group;" ::: "memory");
    };

    float acc[4][4][4];
#pragma unroll
    for (int mi = 0; mi < 4; mi++)
#pragma unroll
        for (int ni = 0; ni < 4; ni++)
#pragma unroll
            for (int r = 0; r < 4; r++) acc[mi][ni][r] = 0.f;

    fill(0); fill(1);

    const int lrow = lane & 15;
    const int lcol = lane >> 4;

    for (int i = 0; i < NCHUNK; i++) {
        int s = i % NSTAGE;
        if (i + 1 < NCHUNK)
            asm volatile("cp.async.wait_group 1;" ::: "memory");
        else
            asm volatile("cp.async.wait_group 0;" ::: "memory");
        __syncthreads();

        if (i + 2 < NCHUNK) fill(i + 2);

        uint32_t Asb = smem_u32(tiles + s * 32768);
        uint32_t Bsb = Asb + 16384;

        // fragment double-buffer over the 4 k16-steps
        uint32_t a[2][4][4], b[2][2][4];
#pragma unroll
        for (int mi = 0; mi < 4; mi++)
            ldsm4(a[0][mi], Asb + SW128((wm + mi * 16 + lrow) * 128 + lcol * 16));
#pragma unroll
        for (int bi = 0; bi < 2; bi++)
            ldsm4(b[0][bi], Bsb + SW128((wn + bi * 16 + lrow) * 128 + lcol * 16));

#pragma unroll
        for (int ks = 0; ks < 4; ks++) {
            int cur = ks & 1, nxt = cur ^ 1;
            if (ks < 3) {
#pragma unroll
                for (int mi = 0; mi < 4; mi++)
                    ldsm4(a[nxt][mi],
                          Asb + SW128((wm + mi * 16 + lrow) * 128 + ((ks + 1) * 2 + lcol) * 16));
#pragma unroll
                for (int bi = 0; bi < 2; bi++)
                    ldsm4(b[nxt][bi],
                          Bsb + SW128((wn + bi * 16 + lrow) * 128 + ((ks + 1) * 2 + lcol) * 16));
            }
#pragma unroll
            for (int mi = 0; mi < 4; mi++)
#pragma unroll
                for (int ni = 0; ni < 4; ni++) {
                    int bi = ni >> 1, hf = ni & 1;
                    mma16816(acc[mi][ni], a[cur][mi], b[cur][bi][hf], b[cur][bi][2 + hf]);
                }
        }
    }

    // epilogue
    const int gr = lane >> 2;
    const int gc = (lane & 3) * 2;
#pragma unroll
    for (int mi = 0; mi < 4; mi++) {
        int m = m0 + wm + mi * 16 + gr;
#pragma unroll
        for (int ni = 0; ni < 4; ni++) {
            int n = n0 + wn + ni * 8 + gc;
            if (n < N_out) {
                float2 v0 = make_float2(acc[mi][ni][0], acc[mi][ni][1]);
                float2 v1 = make_float2(acc[mi][ni][2], acc[mi][ni][3]);
                *(float2*)&C[(size_t)m * ldc + n]       = v0;
                *(float2*)&C[(size_t)(m + 8) * ldc + n] = v1;
            }
        }
    }
}

// ============================================================
// depthwise causal conv (DCONV=4) + bias — register-blocked 4ch x 4t
// ============================================================
__global__ __launch_bounds__(256)
void conv_kernel(const float* __restrict__ cw, const float* __restrict__ cb)
{
    int c4 = blockIdx.x * 256 + threadIdx.x;   // 0..1279
    int ch = c4 * 4;
    int m0 = blockIdx.y * 4;
    int t0 = m0 & (LSEQ - 1);

    const float4* wp = (const float4*)(cw + ch * 4);
    float4 w0 = wp[0], w1 = wp[1], w2 = wp[2], w3 = wp[3];
    float4 bias = *(const float4*)(cb + ch);

    float4 r[7];
    const float* base = g_xbcza + (size_t)m0 * NPROJ + ch;
#pragma unroll
    for (int k = 0; k < 7; k++) {
        int tt = t0 - 3 + k;
        if (tt >= 0)
            r[k] = *(const float4*)(base + (long)(k - 3) * NPROJ);
        else
            r[k] = make_float4(0.f, 0.f, 0.f, 0.f);
    }

    float* outbase = g_conv + (size_t)m0 * CONVD + ch;
#pragma unroll
    for (int j = 0; j < 4; j++) {
        float4 o = bias;
        o.x += w0.x * r[j].x + w0.y * r[j+1].x + w0.z * r[j+2].x + w0.w * r[j+3].x;
        o.y += w1.x * r[j].y + w1.y * r[j+1].y + w1.z * r[j+2].y + w1.w * r[j+3].y;
        o.z += w2.x * r[j].z + w2.y * r[j+1].z + w2.z * r[j+2].z + w2.w * r[j+3].z;
        o.w += w3.x * r[j].w + w3.y * r[j+1].w + w3.z * r[j+2].w + w3.w * r[j+3].w;
        *(float4*)(outbase + (size_t)j * CONVD) = o;
    }
}

// ============================================================
// per-(b,chunk,head) SSD chunk kernel
// ============================================================
__global__ __launch_bounds__(256)
void chunk_kernel()
{
    extern __shared__ float sm[];
    float* CsT = sm;               // [64][132]
    float* BsT = sm + 8448;        // [64][132]
    float* Xs  = sm + 16896;       // [128][36]
    float* MsT = sm + 21504;       // [128][132]
    float* sA  = sm + 38400;       // [128]
    float* sDs = sm + 38528;       // [128]

    const int tid = threadIdx.x;
    const int bid = blockIdx.x;
    const int h = bid & 31;
    const int c = (bid >> 5) & 63;
    const int b = bid >> 11;
    const size_t m0 = (size_t)b * LSEQ + (size_t)c * CHK;

    {
        int n = tid & 63, lb = tid >> 6;
        for (int l = lb; l < CHK; l += 4) {
            const float* row = &g_conv[(m0 + l) * CONVD];
            BsT[n * 132 + l] = row[DINNER + h * DST + n];
            CsT[n * 132 + l] = row[DINNER + NH * DST + h * DST + n];
        }
        int p = tid & 31, lb2 = tid >> 5;
        for (int l = lb2; l < CHK; l += 8)
            Xs[l * 36 + p] = g_conv[(m0 + l) * CONVD + h * HDIM + p];
    }

    if (tid < CHK) {
        float alog = g_xbcza[(m0 + tid) * NPROJ + (CONVD + DINNER) + h];
        float dt = alog > 20.f ? alog : log1pf(expf(alog));
        sA[tid] = dt;
    }
    __syncthreads();
    for (int off = 1; off < CHK; off <<= 1) {
        float v = 0.f;
        if (tid < CHK && tid >= off) v = sA[tid - off];
        __syncthreads();
        if (tid < CHK) sA[tid] += v;
        __syncthreads();
    }
    if (tid < CHK) sA[tid] = -sA[tid];
    __syncthreads();
    float aLast = sA[CHK - 1];
    if (tid < CHK) {
        sDs[tid] = __expf(aLast - sA[tid]);
        g_acum[(m0 + tid) * NH + h] = sA[tid];
    }
    if (tid == 0) g_dc[(b * NCH + c) * NH + h] = __expf(aLast);
    __syncthreads();

    const int txp = tid & 15, typ = tid >> 4;
    const int l0 = typ * 8, s0 = txp * 8;
    if (typ < txp) {
#pragma unroll
        for (int j = 0; j < 8; j++)
#pragma unroll
            for (int i = 0; i < 8; i++)
                MsT[(s0 + j) * 132 + l0 + i] = 0.f;
    } else {
        float acc[8][8];
#pragma unroll
        for (int i = 0; i < 8; i++)
#pragma unroll
            for (int j = 0; j < 8; j++) acc[i][j] = 0.f;

        for (int n = 0; n < DST; n++) {
            float a[8], bb[8];
            float4 t0 = *(float4*)&CsT[n * 132 + l0];
            float4 t1 = *(float4*)&CsT[n * 132 + l0 + 4];
            float4 u0 = *(float4*)&BsT[n * 132 + s0];
            float4 u1 = *(float4*)&BsT[n * 132 + s0 + 4];
            a[0]=t0.x; a[1]=t0.y; a[2]=t0.z; a[3]=t0.w;
            a[4]=t1.x; a[5]=t1.y; a[6]=t1.z; a[7]=t1.w;
            bb[0]=u0.x; bb[1]=u0.y; bb[2]=u0.z; bb[3]=u0.w;
            bb[4]=u1.x; bb[5]=u1.y; bb[6]=u1.z; bb[7]=u1.w;
#pragma unroll
            for (int i = 0; i < 8; i++)
#pragma unroll
                for (int j = 0; j < 8; j++)
                    acc[i][j] += a[i] * bb[j];
        }
        float as0 = sA[s0];
        float el[8], es[8];
#pragma unroll
        for (int i = 0; i < 8; i++) el[i] = __expf(sA[l0 + i] - as0);
#pragma unroll
        for (int j = 0; j < 8; j++) es[j] = __expf(as0 - sA[s0 + j]);
#pragma unroll
        for (int j = 0; j < 8; j++)
#pragma unroll
            for (int i = 0; i < 8; i++) {
                float v = acc[i][j] * el[i] * es[j];
                if (typ == txp && i < j) v = 0.f;
                MsT[(s0 + j) * 132 + l0 + i] = v;
            }
    }
    __syncthreads();

    {
        const int p = tid & 31, lg = tid >> 5;
        const int lb = lg * 16;
        float yacc[16];
#pragma unroll
        for (int i = 0; i < 16; i++) yacc[i] = 0.f;
        for (int s = 0; s < CHK; s++) {
            float xv = Xs[s * 36 + p];
#pragma unroll
            for (int q = 0; q < 4; q++) {
                float4 mm = *(float4*)&MsT[s * 132 + lb + q * 4];
                yacc[q*4+0] += mm.x * xv;
                yacc[q*4+1] += mm.y * xv;
                yacc[q*4+2] += mm.z * xv;
                yacc[q*4+3] += mm.w * xv;
            }
        }
#pragma unroll
        for (int i = 0; i < 16; i++)
            g_y[(m0 + lb + i) * DINNER + h * HDIM + p] = yacc[i];
    }

    {
        const int n = tid & 63, pg = tid >> 6;
        float st[8];
#pragma unroll
        for (int i = 0; i < 8; i++) st[i] = 0.f;
        for (int s = 0; s < CHK; s++) {
            float w = BsT[n * 132 + s] * sDs[s];
            float4 x0 = *(float4*)&Xs[s * 36 + pg * 8];
            float4 x1 = *(float4*)&Xs[s * 36 + pg * 8 + 4];
            st[0] += w * x0.x; st[1] += w * x0.y; st[2] += w * x0.z; st[3] += w * x0.w;
            st[4] += w * x1.x; st[5] += w * x1.y; st[6] += w * x1.z; st[7] += w * x1.w;
        }
        size_t sb = ((size_t)((b * NCH + c) * NH + h)) * (HDIM * DST);
#pragma unroll
        for (int i = 0; i < 8; i++)
            g_states[sb + (pg * 8 + i) * DST + n] = st[i];
    }
}

// ============================================================
// inter-chunk state scan
// ============================================================
__global__ __launch_bounds__(512)
void scan_kernel()
{
    int b = blockIdx.x >> 5, h = blockIdx.x & 31;
    int tid = threadIdx.x;
    float4 S = make_float4(0.f, 0.f, 0.f, 0.f);
    for (int c = 0; c < NCH; c++) {
        size_t base = ((size_t)((b * NCH + c) * NH + h)) * (HDIM * DST);
        float4 stv = *(const float4*)&g_states[base + tid * 4];
        *(float4*)&g_prevs[base + tid * 4] = S;
        float d = g_dc[(b * NCH + c) * NH + h];
        S.x = S.x * d + stv.x;
        S.y = S.y * d + stv.y;
        S.z = S.z * d + stv.z;
        S.w = S.w * d + stv.w;
    }
}

// ============================================================
// Y_off + D*x skip + SiLU gating, fused bf16 split output -> g_yS [hi|lo]
// ============================================================
__global__ __launch_bounds__(256)
void yoff_kernel(const float* __restrict__ Dvec, const float* __restrict__ z_bias)
{
    extern __shared__ float sm[];
    float* Cs = sm;            // [128][68]
    float* Pv = sm + 128*68;   // [32][68]
    float* eA = sm + 128*68 + 32*68;  // [128]

    const int tid = threadIdx.x;
    const int bid = blockIdx.x;
    const int h = bid & 31;
    const int c = (bid >> 5) & 63;
    const int b = bid >> 11;
    const size_t m0 = (size_t)b * LSEQ + (size_t)c * CHK;
    const size_t pbase = ((size_t)((b * NCH + c) * NH + h)) * (HDIM * DST);

    for (int i = tid; i < CHK * DST; i += 256) {
        int l = i >> 6, n = i & 63;
        Cs[l * 68 + n] = g_conv[(m0 + l) * CONVD + DINNER + NH * DST + h * DST + n];
    }
    for (int i = tid; i < HDIM * DST; i += 256) {
        int p = i >> 6, n = i & 63;
        Pv[p * 68 + n] = g_prevs[pbase + i];
    }
    if (tid < CHK)
        eA[tid] = __expf(g_acum[(m0 + tid) * NH + h]);
    __syncthreads();

    const int p = tid & 31, lg = tid >> 5;
    float4 vp[16];
#pragma unroll
    for (int q = 0; q < 16; q++)
        vp[q] = *(float4*)&Pv[p * 68 + q * 4];
    const float Dh = Dvec[h];
    const int col = h * HDIM + p;
    const float zb = z_bias[col];

#pragma unroll 4
    for (int li = 0; li < 16; li++) {
        int l = lg * 16 + li;
        float acc = 0.f;
#pragma unroll
        for (int q = 0; q < 16; q++) {
            float4 c4 = *(float4*)&Cs[l * 68 + q * 4];
            acc += c4.x * vp[q].x + c4.y * vp[q].y + c4.z * vp[q].z + c4.w * vp[q].w;
        }
        size_t mr = m0 + l;
        float xv = g_conv[mr * CONVD + h * HDIM + p];
        float yv = g_y[mr * DINNER + col] + eA[l] * acc + Dh * xv;
        float zz = g_xbcza[mr * NPROJ + CONVD + col] + zb;
        float sg = 1.f / (1.f + __expf(-zz));
        float gv = yv * (zz * sg);
        __nv_bfloat16 hi = __float2bfloat16(gv);
        __nv_bfloat16 lo = __float2bfloat16(gv - __bfloat162float(hi));
        __nv_bfloat16* yr = g_yS + mr * (size_t)K2;
        yr[col] = hi; yr[1024 + col] = lo;
    }
}

// ============================================================
// launch
// ============================================================
extern "C" void kernel_launch(void* const* d_in, const int* in_sizes, int n_in,
                              void* d_out, int out_size)
{
    (void)in_sizes; (void)n_in; (void)out_size;
    const float* u      = (const float*)d_in[0];
    const float* W_in   = (const float*)d_in[1];
    const float* conv_w = (const float*)d_in[2];
    const float* conv_b = (const float*)d_in[3];
    const float* z_bias = (const float*)d_in[4];
    const float* Dv     = (const float*)d_in[5];
    const float* W_out  = (const float*)d_in[6];
    float* out = (float*)d_out;

    float *p_xbcza = nullptr;
    __nv_bfloat16 *p_uS = nullptr, *p_WinS = nullptr, *p_yS = nullptr, *p_WoutS = nullptr;
    cudaGetSymbolAddress((void**)&p_xbcza, g_xbcza);
    cudaGetSymbolAddress((void**)&p_uS, g_uS);
    cudaGetSymbolAddress((void**)&p_WinS, g_WinS);
    cudaGetSymbolAddress((void**)&p_yS, g_yS);
    cudaGetSymbolAddress((void**)&p_WoutS, g_WoutS);

    static const size_t GEMM_SMEM = NSTAGE * 32768;  // 96 KB
    cudaFuncSetAttribute(gemm_mma, cudaFuncAttributeMaxDynamicSharedMemorySize, (int)GEMM_SMEM);
    cudaFuncSetAttribute(chunk_kernel, cudaFuncAttributeMaxDynamicSharedMemorySize, 155 * 1024);
    cudaFuncSetAttribute(yoff_kernel,  cudaFuncAttributeMaxDynamicSharedMemorySize, 48 * 1024);

    // 0) splits for GEMM1 ([hi|lo] compact)
    split2<<<MROWS * 2, 256>>>(u, p_uS);
    split2<<<NPROJ * 2, 256>>>(W_in, p_WinS);

    // 1) in-proj GEMM: xBCzA[M, 6176]
    {
        dim3 grid((NPROJ + BN - 1) / BN, MROWS / BM);   // (49, 128)
        gemm_mma<<<grid, 256, GEMM_SMEM>>>(p_xbcza, p_uS, p_WinS, NPROJ, NPROJ);
    }
    // 2) causal depthwise conv
    {
        dim3 grid(CONVD / 1024, MROWS / 4);   // (5, 4096)
        conv_kernel<<<grid, 256>>>(conv_w, conv_b);
    }
    // 3) per-chunk SSD
    {
        size_t smem = 38656 * sizeof(float);
        chunk_kernel<<<BATCH * NCH * NH, 256, smem>>>();
    }
    // 4) inter-chunk scan
    scan_kernel<<<BATCH * NH, 512>>>();
    // 5) Y_off + skip + gate (writes compact bf16 split directly)
    {
        size_t smem = (128 * 68 + 32 * 68 + 128) * sizeof(float);
        yoff_kernel<<<BATCH * NCH * NH, 256, smem>>>(Dv, z_bias);
    }
    // 6) out-proj GEMM
    split2<<<1024 * 2, 256>>>(W_out, p_WoutS);
    {
        dim3 grid(1024 / BN, MROWS / BM);               // (8, 128)
        gemm_mma<<<grid, 256, GEMM_SMEM>>>(out, p_yS, p_WoutS, 1024, 1024);
    }
}

// round 10
// speedup vs baseline: 1.1487x; 1.0981x over previous
#include <cuda_runtime.h>
#include <cuda_bf16.h>
#include <math.h>
#include <stdint.h>

// ---------------- problem constants ----------------
#define BATCH  2
#define LSEQ   8192
#define DMODEL 1024
#define NPROJ  6176    // 2*D_INNER + 2*NQK*DSTATE + NV
#define CONVD  5120    // D_INNER + 2*NQK*DSTATE
#define DINNER 1024
#define NH     32
#define DST    64
#define HDIM   32
#define CHK    128
#define NCH    64
#define MROWS  (BATCH*LSEQ)   // 16384

// split-bf16 GEMM constants
#define K2     2048            // stored: [hi | lo]
#define BM     128
#define BN     128
#define BK     64
#define NSTAGE 3
#define NCHUNK 48              // logical K = 3072
#define NPROJ_PAD 6400

// ---------------- scratch (device globals) --------
__device__ float g_xbcza[(size_t)MROWS * NPROJ];
__device__ float g_conv [(size_t)MROWS * CONVD];
__device__ float g_acum [(size_t)MROWS * NH];
__device__ float g_y    [(size_t)MROWS * DINNER];   // Y_diag
__device__ float g_states[(size_t)BATCH*NCH*NH*HDIM*DST];
__device__ float g_prevs [(size_t)BATCH*NCH*NH*HDIM*DST];
__device__ float g_dc   [BATCH*NCH*NH];

__device__ __nv_bfloat16 g_uS   [(size_t)MROWS * K2];
__device__ __nv_bfloat16 g_WinS [(size_t)NPROJ_PAD * K2];
__device__ __nv_bfloat16 g_yS   [(size_t)MROWS * K2];
__device__ __nv_bfloat16 g_WoutS[(size_t)1024 * K2];

// ---------------- helpers ----------------
__device__ __forceinline__ uint32_t smem_u32(const void* p) {
    uint32_t a;
    asm("{ .reg .u64 t; cvta.to.shared.u64 t, %1; cvt.u32.u64 %0, t; }"
        : "=r"(a) : "l"(p));
    return a;
}
#define SW128(o) ((o) ^ (((o) >> 3) & 0x70))

__device__ __forceinline__ void ldsm4(uint32_t* r, uint32_t addr) {
    asm volatile("ldmatrix.sync.aligned.m8n8.x4.shared.b16 {%0,%1,%2,%3}, [%4];"
        : "=r"(r[0]), "=r"(r[1]), "=r"(r[2]), "=r"(r[3]) : "r"(addr));
}
__device__ __forceinline__ void mma16816(float* c, const uint32_t* a,
                                         uint32_t b0, uint32_t b1) {
    asm volatile(
        "mma.sync.aligned.m16n8k16.row.col.f32.bf16.bf16.f32 "
        "{%0,%1,%2,%3}, {%4,%5,%6,%7}, {%8,%9}, {%0,%1,%2,%3};"
        : "+f"(c[0]), "+f"(c[1]), "+f"(c[2]), "+f"(c[3])
        : "r"(a[0]), "r"(a[1]), "r"(a[2]), "r"(a[3]), "r"(b0), "r"(b1));
}
__device__ __forceinline__ uint32_t pack2(__nv_bfloat16 a, __nv_bfloat16 b) {
    return (uint32_t)__bfloat16_as_ushort(a) | ((uint32_t)__bfloat16_as_ushort(b) << 16);
}

// ============================================================
// split kernel: fp32 [M,1024] -> bf16 [M,2048] as [hi|lo]
// ============================================================
__global__ __launch_bounds__(256)
void split2(const float* __restrict__ X, __nv_bfloat16* __restrict__ Y)
{
    size_t idx = (size_t)blockIdx.x * 256 + threadIdx.x;
    size_t m = idx >> 9;
    int k2 = (int)(idx & 511) * 2;
    float2 x = *(const float2*)&X[m * 1024 + k2];
    __nv_bfloat16 h0 = __float2bfloat16(x.x);
    __nv_bfloat16 h1 = __float2bfloat16(x.y);
    __nv_bfloat16 l0 = __float2bfloat16(x.x - __bfloat162float(h0));
    __nv_bfloat16 l1 = __float2bfloat16(x.y - __bfloat162float(h1));
    __nv_bfloat162 hi; hi.x = h0; hi.y = h1;
    __nv_bfloat162 lo; lo.x = l0; lo.y = l1;
    __nv_bfloat16* row = Y + m * (size_t)K2;
    *(__nv_bfloat162*)&row[k2]        = hi;
    *(__nv_bfloat162*)&row[1024 + k2] = lo;
}

// ============================================================
// bf16 warp-MMA GEMM (R6/R8 known-good shape)
// ============================================================
__global__ __launch_bounds__(256, 2)
void gemm_mma(float* __restrict__ C,
              const __nv_bfloat16* __restrict__ A,
              const __nv_bfloat16* __restrict__ B,
              int N_out, int ldc)
{
    extern __shared__ char smem[];
    const int tid  = threadIdx.x;
    const int wid  = tid >> 5;
    const int lane = tid & 31;
    const int m0 = blockIdx.y * BM;
    const int n0 = blockIdx.x * BN;
    const int wm = (wid >> 2) * 64;
    const int wn = (wid & 3) * 32;

    char* tiles = smem;

    auto fill = [&](int chunk) {
        int s = chunk % NSTAGE;
        int part = chunk >> 4;
        int ko = (chunk & 15) * BK;
        int aoff = (part == 1) ? 1024 : 0;
        int boff = (part == 2) ? 1024 : 0;
        char* As = tiles + s * 32768;
        char* Bs = As + 16384;
        const char* Ag = (const char*)(A + (size_t)m0 * K2 + aoff + ko);
        const char* Bg = (const char*)(B + (size_t)n0 * K2 + boff + ko);
        uint32_t Asb = smem_u32(As), Bsb = smem_u32(Bs);
#pragma unroll
        for (int r = 0; r < 4; r++) {
            int cid = tid + r * 256;
            int row = cid >> 3, col = cid & 7;
            uint32_t dst = Asb + SW128(row * 128 + col * 16);
            const void* src = Ag + (size_t)row * (K2 * 2) + col * 16;
            asm volatile("cp.async.cg.shared.global [%0], [%1], 16;" :: "r"(dst), "l"(src));
        }
#pragma unroll
        for (int r = 0; r < 4; r++) {
            int cid = tid + r * 256;
            int row = cid >> 3, col = cid & 7;
            uint32_t dst = Bsb + SW128(row * 128 + col * 16);
            const void* src = Bg + (size_t)row * (K2 * 2) + col * 16;
            asm volatile("cp.async.cg.shared.global [%0], [%1], 16;" :: "r"(dst), "l"(src));
        }
        asm volatile("cp.async.commit_group;" ::: "memory");
    };

    float acc[4][4][4];
#pragma unroll
    for (int mi = 0; mi < 4; mi++)
#pragma unroll
        for (int ni = 0; ni < 4; ni++)
#pragma unroll
            for (int r = 0; r < 4; r++) acc[mi][ni][r] = 0.f;

    fill(0); fill(1);

    const int lrow = lane & 15;
    const int lcol = lane >> 4;

    for (int i = 0; i < NCHUNK; i++) {
        int s = i % NSTAGE;
        if (i + 1 < NCHUNK)
            asm volatile("cp.async.wait_group 1;" ::: "memory");
        else
            asm volatile("cp.async.wait_group 0;" ::: "memory");
        __syncthreads();

        if (i + 2 < NCHUNK) fill(i + 2);

        uint32_t Asb = smem_u32(tiles + s * 32768);
        uint32_t Bsb = Asb + 16384;

#pragma unroll
        for (int ks = 0; ks < 4; ks++) {
            uint32_t a[4][4], b[2][4];
#pragma unroll
            for (int mi = 0; mi < 4; mi++)
                ldsm4(a[mi], Asb + SW128((wm + mi * 16 + lrow) * 128 + (ks * 2 + lcol) * 16));
#pragma unroll
            for (int bi = 0; bi < 2; bi++)
                ldsm4(b[bi], Bsb + SW128((wn + bi * 16 + lrow) * 128 + (ks * 2 + lcol) * 16));
#pragma unroll
            for (int mi = 0; mi < 4; mi++)
#pragma unroll
                for (int ni = 0; ni < 4; ni++) {
                    int bi = ni >> 1, hf = ni & 1;
                    mma16816(acc[mi][ni], a[mi], b[bi][hf], b[bi][2 + hf]);
                }
        }
    }

    const int gr = lane >> 2;
    const int gc = (lane & 3) * 2;
#pragma unroll
    for (int mi = 0; mi < 4; mi++) {
        int m = m0 + wm + mi * 16 + gr;
#pragma unroll
        for (int ni = 0; ni < 4; ni++) {
            int n = n0 + wn + ni * 8 + gc;
            if (n < N_out) {
                float2 v0 = make_float2(acc[mi][ni][0], acc[mi][ni][1]);
                float2 v1 = make_float2(acc[mi][ni][2], acc[mi][ni][3]);
                *(float2*)&C[(size_t)m * ldc + n]       = v0;
                *(float2*)&C[(size_t)(m + 8) * ldc + n] = v1;
            }
        }
    }
}

// ============================================================
// depthwise causal conv (register-blocked 4ch x 4t)
// ============================================================
__global__ __launch_bounds__(256)
void conv_kernel(const float* __restrict__ cw, const float* __restrict__ cb)
{
    int c4 = blockIdx.x * 256 + threadIdx.x;
    int ch = c4 * 4;
    int m0 = blockIdx.y * 4;
    int t0 = m0 & (LSEQ - 1);

    const float4* wp = (const float4*)(cw + ch * 4);
    float4 w0 = wp[0], w1 = wp[1], w2 = wp[2], w3 = wp[3];
    float4 bias = *(const float4*)(cb + ch);

    float4 r[7];
    const float* base = g_xbcza + (size_t)m0 * NPROJ + ch;
#pragma unroll
    for (int k = 0; k < 7; k++) {
        int tt = t0 - 3 + k;
        if (tt >= 0)
            r[k] = *(const float4*)(base + (long)(k - 3) * NPROJ);
        else
            r[k] = make_float4(0.f, 0.f, 0.f, 0.f);
    }

    float* outbase = g_conv + (size_t)m0 * CONVD + ch;
#pragma unroll
    for (int j = 0; j < 4; j++) {
        float4 o = bias;
        o.x += w0.x * r[j].x + w0.y * r[j+1].x + w0.z * r[j+2].x + w0.w * r[j+3].x;
        o.y += w1.x * r[j].y + w1.y * r[j+1].y + w1.z * r[j+2].y + w1.w * r[j+3].y;
        o.z += w2.x * r[j].z + w2.y * r[j+1].z + w2.z * r[j+2].z + w2.w * r[j+3].z;
        o.w += w3.x * r[j].w + w3.y * r[j+1].w + w3.z * r[j+2].w + w3.w * r[j+3].w;
        *(float4*)(outbase + (size_t)j * CONVD) = o;
    }
}

// ============================================================
// per-(b,chunk,head) SSD chunk kernel — tensor-core version.
// smem byte map (dynamic):
//   phase1: C_hi@0  C_lo@16K  B_hi@32K  B_lo@48K   (each [128][64] bf16, 128B rows)
//   after:  M_hi k0@0 k1@16K ; M_lo k0@32K k1@48K  (overlay)
//   Xt_hi@64K (+4K per kb), Xt_lo@72K               ([32][64] bf16 blocks)
//   Btd_hi@80K (+8K per kb), Btd_lo@96K             ([64][64] bf16 blocks)
//   sA@112K, sDs — total ~113K
// ============================================================
#define CH_C_HI   0u
#define CH_C_LO   16384u
#define CH_B_HI   32768u
#define CH_B_LO   49152u
#define CH_M_HI   0u
#define CH_M_LO   32768u
#define CH_XT_HI  65536u
#define CH_XT_LO  73728u
#define CH_BTD_HI 81920u
#define CH_BTD_LO 98304u
#define CH_SA     114688u
#define CH_SDS    115200u
#define CH_SMEM   115712u

__global__ __launch_bounds__(256)
void chunk_kernel()
{
    extern __shared__ char smem[];
    float* sA  = (float*)(smem + CH_SA);
    float* sDs = (float*)(smem + CH_SDS);
    const uint32_t sb0 = smem_u32(smem);

    const int tid = threadIdx.x;
    const int wid = tid >> 5, lane = tid & 31;
    const int bid = blockIdx.x;
    const int h = bid & 31;
    const int c = (bid >> 5) & 63;
    const int b = bid >> 11;
    const size_t m0 = (size_t)b * LSEQ + (size_t)c * CHK;

    // ---- dt = softplus(A_log); inclusive scan of -dt ----
    if (tid < CHK) {
        float alog = g_xbcza[(m0 + tid) * NPROJ + (CONVD + DINNER) + h];
        float dt = alog > 20.f ? alog : log1pf(expf(alog));
        sA[tid] = dt;
    }
    __syncthreads();
    for (int off = 1; off < CHK; off <<= 1) {
        float v = 0.f;
        if (tid < CHK && tid >= off) v = sA[tid - off];
        __syncthreads();
        if (tid < CHK) sA[tid] += v;
        __syncthreads();
    }
    if (tid < CHK) sA[tid] = -sA[tid];
    __syncthreads();
    float aLast = sA[CHK - 1];
    if (tid < CHK) {
        sDs[tid] = __expf(aLast - sA[tid]);
        g_acum[(m0 + tid) * NH + h] = sA[tid];
    }
    if (tid == 0) g_dc[(b * NCH + c) * NH + h] = __expf(aLast);
    __syncthreads();

    // ---- convert C,B -> bf16 hi/lo tiles ----
    for (int u = tid; u < 128 * 16; u += 256) {
        int l = u >> 4, nq = (u & 15) * 4;
        const float* crow = &g_conv[(m0 + l) * CONVD];
        float4 vc = *(const float4*)&crow[DINNER + NH * DST + h * DST + nq];
        float4 vb = *(const float4*)&crow[DINNER + h * DST + nq];
        uint32_t off = SW128((uint32_t)(l * 128 + nq * 2));
        {
            __nv_bfloat16 h0 = __float2bfloat16(vc.x), h1 = __float2bfloat16(vc.y);
            __nv_bfloat16 h2 = __float2bfloat16(vc.z), h3 = __float2bfloat16(vc.w);
            *(uint2*)(smem + CH_C_HI + off) = make_uint2(pack2(h0, h1), pack2(h2, h3));
            __nv_bfloat16 q0 = __float2bfloat16(vc.x - __bfloat162float(h0));
            __nv_bfloat16 q1 = __float2bfloat16(vc.y - __bfloat162float(h1));
            __nv_bfloat16 q2 = __float2bfloat16(vc.z - __bfloat162float(h2));
            __nv_bfloat16 q3 = __float2bfloat16(vc.w - __bfloat162float(h3));
            *(uint2*)(smem + CH_C_LO + off) = make_uint2(pack2(q0, q1), pack2(q2, q3));
        }
        {
            __nv_bfloat16 h0 = __float2bfloat16(vb.x), h1 = __float2bfloat16(vb.y);
            __nv_bfloat16 h2 = __float2bfloat16(vb.z), h3 = __float2bfloat16(vb.w);
            *(uint2*)(smem + CH_B_HI + off) = make_uint2(pack2(h0, h1), pack2(h2, h3));
            __nv_bfloat16 q0 = __float2bfloat16(vb.x - __bfloat162float(h0));
            __nv_bfloat16 q1 = __float2bfloat16(vb.y - __bfloat162float(h1));
            __nv_bfloat16 q2 = __float2bfloat16(vb.z - __bfloat162float(h2));
            __nv_bfloat16 q3 = __float2bfloat16(vb.w - __bfloat162float(h3));
            *(uint2*)(smem + CH_B_LO + off) = make_uint2(pack2(q0, q1), pack2(q2, q3));
        }
    }
    // ---- Btd[n][s] = B[s][n] * ds[s], transposed bf16 hi/lo ----
    for (int u = tid; u < 128 * 16; u += 256) {
        int s = u >> 4, nq = (u & 15) * 4;
        float d = sDs[s];
        float4 v = *(const float4*)&g_conv[(m0 + s) * CONVD + DINNER + h * DST + nq];
        float vv[4] = {v.x * d, v.y * d, v.z * d, v.w * d};
        uint32_t kb = (uint32_t)(s >> 6), cs = (uint32_t)((s & 63) * 2);
#pragma unroll
        for (int j = 0; j < 4; j++) {
            __nv_bfloat16 hh = __float2bfloat16(vv[j]);
            __nv_bfloat16 ll = __float2bfloat16(vv[j] - __bfloat162float(hh));
            uint32_t off = SW128((uint32_t)((nq + j) * 128) + cs);
            *(__nv_bfloat16*)(smem + CH_BTD_HI + kb * 8192 + off) = hh;
            *(__nv_bfloat16*)(smem + CH_BTD_LO + kb * 8192 + off) = ll;
        }
    }
    // ---- Xt[p][s] = X[s][p], transposed bf16 hi/lo ----
    for (int u = tid; u < 128 * 8; u += 256) {
        int s = u >> 3, pq = (u & 7) * 4;
        float4 v = *(const float4*)&g_conv[(m0 + s) * CONVD + h * HDIM + pq];
        float vv[4] = {v.x, v.y, v.z, v.w};
        uint32_t kb = (uint32_t)(s >> 6), cs = (uint32_t)((s & 63) * 2);
#pragma unroll
        for (int j = 0; j < 4; j++) {
            __nv_bfloat16 hh = __float2bfloat16(vv[j]);
            __nv_bfloat16 ll = __float2bfloat16(vv[j] - __bfloat162float(hh));
            uint32_t off = SW128((uint32_t)((pq + j) * 128) + cs);
            *(__nv_bfloat16*)(smem + CH_XT_HI + kb * 4096 + off) = hh;
            *(__nv_bfloat16*)(smem + CH_XT_LO + kb * 4096 + off) = ll;
        }
    }
    __syncthreads();

    const int lrow = lane & 15, lcol = lane >> 4;
    const int gr = lane >> 2, gc = (lane & 3) * 2;

    // ---- phase 1: G = C.B^T (3-term split), warp grid 2x4, K=64 ----
    const int wm = (wid >> 2) * 64;
    const int wn = (wid & 3) * 32;
    float acc[4][4][4];
#pragma unroll
    for (int mi = 0; mi < 4; mi++)
#pragma unroll
        for (int ni = 0; ni < 4; ni++)
#pragma unroll
            for (int r = 0; r < 4; r++) acc[mi][ni][r] = 0.f;

    if (!(wm == 0 && wn >= 64)) {   // skip fully-masked warp tiles
#pragma unroll
        for (int pt = 0; pt < 3; pt++) {
            uint32_t Ab = sb0 + ((pt == 1) ? CH_C_LO : CH_C_HI);
            uint32_t Bb = sb0 + ((pt == 2) ? CH_B_LO : CH_B_HI);
#pragma unroll
            for (int ks = 0; ks < 4; ks++) {       // FIXED: K=64 -> 4 k16 steps
                uint32_t a[4][4], bb[2][4];
#pragma unroll
                for (int mi = 0; mi < 4; mi++)
                    ldsm4(a[mi], Ab + SW128((wm + mi * 16 + lrow) * 128 + (ks * 2 + lcol) * 16));
#pragma unroll
                for (int bi = 0; bi < 2; bi++)
                    ldsm4(bb[bi], Bb + SW128((wn + bi * 16 + lrow) * 128 + (ks * 2 + lcol) * 16));
#pragma unroll
                for (int mi = 0; mi < 4; mi++)
#pragma unroll
                    for (int ni = 0; ni < 4; ni++) {
                        int bi = ni >> 1, hf = ni & 1;
                        mma16816(acc[mi][ni], a[mi], bb[bi][hf], bb[bi][2 + hf]);
                    }
            }
        }
    }
    __syncthreads();   // all phase-1 reads of C/B done

    // ---- epilogue: decay+mask, split M -> smem (overlay C/B area) ----
#pragma unroll
    for (int ni = 0; ni < 4; ni++) {
        int s0 = wn + ni * 8;
        float aref = sA[s0];
        int sa = s0 + gc, sb = s0 + gc + 1;
        float es0 = __expf(aref - sA[sa]);
        float es1 = __expf(aref - sA[sb]);
        uint32_t kb = (uint32_t)(s0 >> 6);
        uint32_t cbyte = (uint32_t)(((s0 & 63) + gc) * 2);
#pragma unroll
        for (int mi = 0; mi < 4; mi++) {
#pragma unroll
            for (int half = 0; half < 2; half++) {
                int l = wm + mi * 16 + gr + half * 8;
                float el = __expf(sA[l] - aref);
                float v0 = (l >= sa) ? acc[mi][ni][half * 2 + 0] * el * es0 : 0.f;
                float v1 = (l >= sb) ? acc[mi][ni][half * 2 + 1] * el * es1 : 0.f;
                __nv_bfloat16 h0 = __float2bfloat16(v0), h1 = __float2bfloat16(v1);
                __nv_bfloat16 q0 = __float2bfloat16(v0 - __bfloat162float(h0));
                __nv_bfloat16 q1 = __float2bfloat16(v1 - __bfloat162float(h1));
                uint32_t off = SW128((uint32_t)(l * 128) + cbyte);
                *(uint32_t*)(smem + CH_M_HI + kb * 16384 + off) = pack2(h0, h1);
                *(uint32_t*)(smem + CH_M_LO + kb * 16384 + off) = pack2(q0, q1);
            }
        }
    }
    __syncthreads();

    // ---- phase 2: Y_diag = M @ X  (3-term), each warp: 16 l-rows x 32 p ----
    {
        const int l16 = wid * 16;
        float y2[4][4];
#pragma unroll
        for (int ni = 0; ni < 4; ni++)
#pragma unroll
            for (int r = 0; r < 4; r++) y2[ni][r] = 0.f;
#pragma unroll
        for (int pt = 0; pt < 3; pt++) {
            uint32_t Ab = sb0 + ((pt == 1) ? CH_M_LO : CH_M_HI);
            uint32_t Bb = sb0 + ((pt == 2) ? CH_XT_LO : CH_XT_HI);
#pragma unroll
            for (int kb = 0; kb < 2; kb++) {
                uint32_t Abuf = Ab + kb * 16384u;
                uint32_t Bbuf = Bb + kb * 4096u;
#pragma unroll
                for (int ks = 0; ks < 4; ks++) {
                    uint32_t a[4], bb[2][4];
                    ldsm4(a, Abuf + SW128((l16 + lrow) * 128 + (ks * 2 + lcol) * 16));
                    ldsm4(bb[0], Bbuf + SW128((lrow) * 128 + (ks * 2 + lcol) * 16));
                    ldsm4(bb[1], Bbuf + SW128((16 + lrow) * 128 + (ks * 2 + lcol) * 16));
#pragma unroll
                    for (int ni = 0; ni < 4; ni++) {
                        int bi = ni >> 1, hf = ni & 1;
                        mma16816(y2[ni], a, bb[bi][hf], bb[bi][2 + hf]);
                    }
                }
            }
        }
#pragma unroll
        for (int ni = 0; ni < 4; ni++) {
            int p = ni * 8 + gc;
            int l = l16 + gr;
            *(float2*)&g_y[(m0 + l) * DINNER + h * HDIM + p] =
                make_float2(y2[ni][0], y2[ni][1]);
            *(float2*)&g_y[(m0 + l + 8) * DINNER + h * HDIM + p] =
                make_float2(y2[ni][2], y2[ni][3]);
        }
    }

    // ---- phase 3: states[p][n] = Xt . Btd (3-term) ----
    {
        const int pm = (wid & 1) * 16;
        const int nn = (wid >> 1) * 16;
        float s3[2][4];
#pragma unroll
        for (int ni = 0; ni < 2; ni++)
#pragma unroll
            for (int r = 0; r < 4; r++) s3[ni][r] = 0.f;
#pragma unroll
        for (int pt = 0; pt < 3; pt++) {
            uint32_t Ab = sb0 + ((pt == 1) ? CH_XT_LO : CH_XT_HI);
            uint32_t Bb = sb0 + ((pt == 2) ? CH_BTD_LO : CH_BTD_HI);
#pragma unroll
            for (int kb = 0; kb < 2; kb++) {
                uint32_t Abuf = Ab + kb * 4096u;
                uint32_t Bbuf = Bb + kb * 8192u;
#pragma unroll
                for (int ks = 0; ks < 4; ks++) {
                    uint32_t a[4], bb[4];
                    ldsm4(a, Abuf + SW128((pm + lrow) * 128 + (ks * 2 + lcol) * 16));
                    ldsm4(bb, Bbuf + SW128((nn + lrow) * 128 + (ks * 2 + lcol) * 16));
                    mma16816(s3[0], a, bb[0], bb[2]);
                    mma16816(s3[1], a, bb[1], bb[3]);
                }
            }
        }
        size_t sbase = ((size_t)((b * NCH + c) * NH + h)) * (HDIM * DST);
#pragma unroll
        for (int ni = 0; ni < 2; ni++) {
            int n = nn + ni * 8 + gc;
            int p0 = pm + gr;
            *(float2*)&g_states[sbase + (size_t)p0 * DST + n] =
                make_float2(s3[ni][0], s3[ni][1]);
            *(float2*)&g_states[sbase + (size_t)(p0 + 8) * DST + n] =
                make_float2(s3[ni][2], s3[ni][3]);
        }
    }
}

// ============================================================
// inter-chunk state scan
// ============================================================
__global__ __launch_bounds__(512)
void scan_kernel()
{
    int b = blockIdx.x >> 5, h = blockIdx.x & 31;
    int tid = threadIdx.x;
    float4 S = make_float4(0.f, 0.f, 0.f, 0.f);
    for (int c = 0; c < NCH; c++) {
        size_t base = ((size_t)((b * NCH + c) * NH + h)) * (HDIM * DST);
        float4 stv = *(const float4*)&g_states[base + tid * 4];
        *(float4*)&g_prevs[base + tid * 4] = S;
        float d = g_dc[(b * NCH + c) * NH + h];
        S.x = S.x * d + stv.x;
        S.y = S.y * d + stv.y;
        S.z = S.z * d + stv.z;
        S.w = S.w * d + stv.w;
    }
}

// ============================================================
// Y_off + D*x skip + SiLU gating, fused bf16 split output -> g_yS [hi|lo]
// ============================================================
__global__ __launch_bounds__(256)
void yoff_kernel(const float* __restrict__ Dvec, const float* __restrict__ z_bias)
{
    extern __shared__ float sm[];
    float* Cs = sm;            // [128][68]
    float* Pv = sm + 128*68;   // [32][68]
    float* eA = sm + 128*68 + 32*68;  // [128]

    const int tid = threadIdx.x;
    const int bid = blockIdx.x;
    const int h = bid & 31;
    const int c = (bid >> 5) & 63;
    const int b = bid >> 11;
    const size_t m0 = (size_t)b * LSEQ + (size_t)c * CHK;
    const size_t pbase = ((size_t)((b * NCH + c) * NH + h)) * (HDIM * DST);

    for (int i = tid; i < CHK * DST; i += 256) {
        int l = i >> 6, n = i & 63;
        Cs[l * 68 + n] = g_conv[(m0 + l) * CONVD + DINNER + NH * DST + h * DST + n];
    }
    for (int i = tid; i < HDIM * DST; i += 256) {
        int p = i >> 6, n = i & 63;
        Pv[p * 68 + n] = g_prevs[pbase + i];
    }
    if (tid < CHK)
        eA[tid] = __expf(g_acum[(m0 + tid) * NH + h]);
    __syncthreads();

    const int p = tid & 31, lg = tid >> 5;
    float4 vp[16];
#pragma unroll
    for (int q = 0; q < 16; q++)
        vp[q] = *(float4*)&Pv[p * 68 + q * 4];
    const float Dh = Dvec[h];
    const int col = h * HDIM + p;
    const float zb = z_bias[col];

#pragma unroll 4
    for (int li = 0; li < 16; li++) {
        int l = lg * 16 + li;
        float acc = 0.f;
#pragma unroll
        for (int q = 0; q < 16; q++) {
            float4 c4 = *(float4*)&Cs[l * 68 + q * 4];
            acc += c4.x * vp[q].x + c4.y * vp[q].y + c4.z * vp[q].z + c4.w * vp[q].w;
        }
        size_t mr = m0 + l;
        float xv = g_conv[mr * CONVD + h * HDIM + p];
        float yv = g_y[mr * DINNER + col] + eA[l] * acc + Dh * xv;
        float zz = g_xbcza[mr * NPROJ + CONVD + col] + zb;
        float sg = 1.f / (1.f + __expf(-zz));
        float gv = yv * (zz * sg);
        __nv_bfloat16 hi = __float2bfloat16(gv);
        __nv_bfloat16 lo = __float2bfloat16(gv - __bfloat162float(hi));
        __nv_bfloat16* yr = g_yS + mr * (size_t)K2;
        yr[col] = hi; yr[1024 + col] = lo;
    }
}

// ============================================================
// launch
// ============================================================
extern "C" void kernel_launch(void* const* d_in, const int* in_sizes, int n_in,
                              void* d_out, int out_size)
{
    (void)in_sizes; (void)n_in; (void)out_size;
    const float* u      = (const float*)d_in[0];
    const float* W_in   = (const float*)d_in[1];
    const float* conv_w = (const float*)d_in[2];
    const float* conv_b = (const float*)d_in[3];
    const float* z_bias = (const float*)d_in[4];
    const float* Dv     = (const float*)d_in[5];
    const float* W_out  = (const float*)d_in[6];
    float* out = (float*)d_out;

    float *p_xbcza = nullptr;
    __nv_bfloat16 *p_uS = nullptr, *p_WinS = nullptr, *p_yS = nullptr, *p_WoutS = nullptr;
    cudaGetSymbolAddress((void**)&p_xbcza, g_xbcza);
    cudaGetSymbolAddress((void**)&p_uS, g_uS);
    cudaGetSymbolAddress((void**)&p_WinS, g_WinS);
    cudaGetSymbolAddress((void**)&p_yS, g_yS);
    cudaGetSymbolAddress((void**)&p_WoutS, g_WoutS);

    static const size_t GEMM_SMEM = NSTAGE * 32768;  // 96 KB
    cudaFuncSetAttribute(gemm_mma, cudaFuncAttributeMaxDynamicSharedMemorySize, (int)GEMM_SMEM);
    cudaFuncSetAttribute(chunk_kernel, cudaFuncAttributeMaxDynamicSharedMemorySize, CH_SMEM);
    cudaFuncSetAttribute(yoff_kernel,  cudaFuncAttributeMaxDynamicSharedMemorySize, 48 * 1024);

    // 0) splits for GEMM1
    split2<<<MROWS * 2, 256>>>(u, p_uS);
    split2<<<NPROJ * 2, 256>>>(W_in, p_WinS);

    // 1) in-proj GEMM
    {
        dim3 grid((NPROJ + BN - 1) / BN, MROWS / BM);
        gemm_mma<<<grid, 256, GEMM_SMEM>>>(p_xbcza, p_uS, p_WinS, NPROJ, NPROJ);
    }
    // 2) causal depthwise conv
    {
        dim3 grid(CONVD / 1024, MROWS / 4);
        conv_kernel<<<grid, 256>>>(conv_w, conv_b);
    }
    // 3) per-chunk SSD (tensor-core)
    chunk_kernel<<<BATCH * NCH * NH, 256, CH_SMEM>>>();
    // 4) inter-chunk scan
    scan_kernel<<<BATCH * NH, 512>>>();
    // 5) Y_off + skip + gate
    {
        size_t smem = (128 * 68 + 32 * 68 + 128) * sizeof(float);
        yoff_kernel<<<BATCH * NCH * NH, 256, smem>>>(Dv, z_bias);
    }
    // 6) out-proj GEMM
    split2<<<1024 * 2, 256>>>(W_out, p_WoutS);
    {
        dim3 grid(1024 / BN, MROWS / BM);
        gemm_mma<<<grid, 256, GEMM_SMEM>>>(out, p_yS, p_WoutS, 1024, 1024);
    }
}

// round 12
// speedup vs baseline: 1.1655x; 1.0146x over previous
#include <cuda_runtime.h>
#include <cuda_bf16.h>
#include <math.h>
#include <stdint.h>

// ---------------- problem constants ----------------
#define BATCH  2
#define LSEQ   8192
#define DMODEL 1024
#define NPROJ  6176
#define CONVD  5120
#define DINNER 1024
#define NH     32
#define DST    64
#define HDIM   32
#define CHK    128
#define NCH    64
#define MROWS  (BATCH*LSEQ)   // 16384

// split-bf16 GEMM constants
#define K2     2048            // stored: [hi | lo]
#define BM     128
#define BN     128
#define BK     64
#define NSTAGE 3
#define NCHUNK 48              // logical K = 3072

// ---------------- scratch (device globals) --------
__device__ float g_xbcza[(size_t)MROWS * NPROJ];
__device__ float g_conv [(size_t)MROWS * CONVD];
__device__ float g_acum [(size_t)MROWS * NH];
__device__ float g_y    [(size_t)MROWS * DINNER];
__device__ float g_states[(size_t)BATCH*NCH*NH*HDIM*DST];
__device__ float g_prevs [(size_t)BATCH*NCH*NH*HDIM*DST];
__device__ float g_dc   [BATCH*NCH*NH];

__device__ __nv_bfloat16 g_uS   [(size_t)MROWS * K2];
__device__ __nv_bfloat16 g_WinS [(size_t)NPROJ * K2 + 1024];
__device__ __nv_bfloat16 g_yS   [(size_t)MROWS * K2];
__device__ __nv_bfloat16 g_WoutS[(size_t)1024 * K2];

// ---------------- helpers ----------------
__device__ __forceinline__ uint32_t smem_u32(const void* p) {
    uint32_t a;
    asm("{ .reg .u64 t; cvta.to.shared.u64 t, %1; cvt.u32.u64 %0, t; }"
        : "=r"(a) : "l"(p));
    return a;
}
#define SW128(o) ((o) ^ (((o) >> 3) & 0x70))

__device__ __forceinline__ void ldsm4(uint32_t* r, uint32_t addr) {
    asm volatile("ldmatrix.sync.aligned.m8n8.x4.shared.b16 {%0,%1,%2,%3}, [%4];"
        : "=r"(r[0]), "=r"(r[1]), "=r"(r[2]), "=r"(r[3]) : "r"(addr));
}
__device__ __forceinline__ void mma16816(float* c, const uint32_t* a,
                                         uint32_t b0, uint32_t b1) {
    asm volatile(
        "mma.sync.aligned.m16n8k16.row.col.f32.bf16.bf16.f32 "
        "{%0,%1,%2,%3}, {%4,%5,%6,%7}, {%8,%9}, {%0,%1,%2,%3};"
        : "+f"(c[0]), "+f"(c[1]), "+f"(c[2]), "+f"(c[3])
        : "r"(a[0]), "r"(a[1]), "r"(a[2]), "r"(a[3]), "r"(b0), "r"(b1));
}
__device__ __forceinline__ uint32_t pack2(__nv_bfloat16 a, __nv_bfloat16 b) {
    return (uint32_t)__bfloat16_as_ushort(a) | ((uint32_t)__bfloat16_as_ushort(b) << 16);
}

// ============================================================
// split kernel: fp32 [M,1024] -> bf16 [M,2048] as [hi|lo]
// ============================================================
__global__ __launch_bounds__(256)
void split2(const float* __restrict__ X, __nv_bfloat16* __restrict__ Y)
{
    size_t idx = (size_t)blockIdx.x * 256 + threadIdx.x;
    size_t m = idx >> 9;
    int k2 = (int)(idx & 511) * 2;
    float2 x = *(const float2*)&X[m * 1024 + k2];
    __nv_bfloat16 h0 = __float2bfloat16(x.x);
    __nv_bfloat16 h1 = __float2bfloat16(x.y);
    __nv_bfloat16 l0 = __float2bfloat16(x.x - __bfloat162float(h0));
    __nv_bfloat16 l1 = __float2bfloat16(x.y - __bfloat162float(h1));
    __nv_bfloat162 hi; hi.x = h0; hi.y = h1;
    __nv_bfloat162 lo; lo.x = l0; lo.y = l1;
    __nv_bfloat16* row = Y + m * (size_t)K2;
    *(__nv_bfloat162*)&row[k2]        = hi;
    *(__nv_bfloat162*)&row[1024 + k2] = lo;
}

// ============================================================
// bf16 warp-MMA GEMM, batch-offset aware
// ============================================================
__global__ __launch_bounds__(256, 2)
void gemm_mma(float* __restrict__ C,
              const __nv_bfloat16* __restrict__ A,
              const __nv_bfloat16* __restrict__ B,
              int N_out, int ldc, int m_base)
{
    extern __shared__ char smem[];
    const int tid  = threadIdx.x;
    const int wid  = tid >> 5;
    const int lane = tid & 31;
    const int m0 = m_base + blockIdx.y * BM;
    const int n0 = blockIdx.x * BN;
    const int wm = (wid >> 2) * 64;
    const int wn = (wid & 3) * 32;

    char* tiles = smem;

    auto fill = [&](int chunk) {
        int s = chunk % NSTAGE;
        int part = chunk >> 4;
        int ko = (chunk & 15) * BK;
        int aoff = (part == 1) ? 1024 : 0;
        int boff = (part == 2) ? 1024 : 0;
        char* As = tiles + s * 32768;
        char* Bs = As + 16384;
        const char* Ag = (const char*)(A + (size_t)m0 * K2 + aoff + ko);
        const char* Bg = (const char*)(B + (size_t)n0 * K2 + boff + ko);
        uint32_t Asb = smem_u32(As), Bsb = smem_u32(Bs);
#pragma unroll
        for (int r = 0; r < 4; r++) {
            int cid = tid + r * 256;
            int row = cid >> 3, col = cid & 7;
            uint32_t dst = Asb + SW128(row * 128 + col * 16);
            const void* src = Ag + (size_t)row * (K2 * 2) + col * 16;
            asm volatile("cp.async.cg.shared.global [%0], [%1], 16;" :: "r"(dst), "l"(src));
        }
#pragma unroll
        for (int r = 0; r < 4; r++) {
            int cid = tid + r * 256;
            int row = cid >> 3, col = cid & 7;
            uint32_t dst = Bsb + SW128(row * 128 + col * 16);
            const void* src = Bg + (size_t)row * (K2 * 2) + col * 16;
            asm volatile("cp.async.cg.shared.global [%0], [%1], 16;" :: "r"(dst), "l"(src));
        }
        asm volatile("cp.async.commit_group;" ::: "memory");
    };

    float acc[4][4][4];
#pragma unroll
    for (int mi = 0; mi < 4; mi++)
#pragma unroll
        for (int ni = 0; ni < 4; ni++)
#pragma unroll
            for (int r = 0; r < 4; r++) acc[mi][ni][r] = 0.f;

    fill(0); fill(1);

    const int lrow = lane & 15;
    const int lcol = lane >> 4;

    for (int i = 0; i < NCHUNK; i++) {
        int s = i % NSTAGE;
        if (i + 1 < NCHUNK)
            asm volatile("cp.async.wait_group 1;" ::: "memory");
        else
            asm volatile("cp.async.wait_group 0;" ::: "memory");
        __syncthreads();

        if (i + 2 < NCHUNK) fill(i + 2);

        uint32_t Asb = smem_u32(tiles + s * 32768);
        uint32_t Bsb = Asb + 16384;

#pragma unroll
        for (int ks = 0; ks < 4; ks++) {
            uint32_t a[4][4], b[2][4];
#pragma unroll
            for (int mi = 0; mi < 4; mi++)
                ldsm4(a[mi], Asb + SW128((wm + mi * 16 + lrow) * 128 + (ks * 2 + lcol) * 16));
#pragma unroll
            for (int bi = 0; bi < 2; bi++)
                ldsm4(b[bi], Bsb + SW128((wn + bi * 16 + lrow) * 128 + (ks * 2 + lcol) * 16));
#pragma unroll
            for (int mi = 0; mi < 4; mi++)
#pragma unroll
                for (int ni = 0; ni < 4; ni++) {
                    int bi = ni >> 1, hf = ni & 1;
                    mma16816(acc[mi][ni], a[mi], b[bi][hf], b[bi][2 + hf]);
                }
        }
    }

    const int gr = lane >> 2;
    const int gc = (lane & 3) * 2;
#pragma unroll
    for (int mi = 0; mi < 4; mi++) {
        int m = m0 + wm + mi * 16 + gr;
#pragma unroll
        for (int ni = 0; ni < 4; ni++) {
            int n = n0 + wn + ni * 8 + gc;
            if (n < N_out) {
                float2 v0 = make_float2(acc[mi][ni][0], acc[mi][ni][1]);
                float2 v1 = make_float2(acc[mi][ni][2], acc[mi][ni][3]);
                *(float2*)&C[(size_t)m * ldc + n]       = v0;
                *(float2*)&C[(size_t)(m + 8) * ldc + n] = v1;
            }
        }
    }
}

// ============================================================
// depthwise causal conv (register-blocked 4ch x 4t), batch-offset aware
// ============================================================
__global__ __launch_bounds__(256)
void conv_kernel(const float* __restrict__ cw, const float* __restrict__ cb, int m_base)
{
    int c4 = blockIdx.x * 256 + threadIdx.x;
    int ch = c4 * 4;
    int m0 = m_base + blockIdx.y * 4;
    int t0 = m0 & (LSEQ - 1);

    const float4* wp = (const float4*)(cw + ch * 4);
    float4 w0 = wp[0], w1 = wp[1], w2 = wp[2], w3 = wp[3];
    float4 bias = *(const float4*)(cb + ch);

    float4 r[7];
    const float* base = g_xbcza + (size_t)m0 * NPROJ + ch;
#pragma unroll
    for (int k = 0; k < 7; k++) {
        int tt = t0 - 3 + k;
        if (tt >= 0)
            r[k] = *(const float4*)(base + (long)(k - 3) * NPROJ);
        else
            r[k] = make_float4(0.f, 0.f, 0.f, 0.f);
    }

    float* outbase = g_conv + (size_t)m0 * CONVD + ch;
#pragma unroll
    for (int j = 0; j < 4; j++) {
        float4 o = bias;
        o.x += w0.x * r[j].x + w0.y * r[j+1].x + w0.z * r[j+2].x + w0.w * r[j+3].x;
        o.y += w1.x * r[j].y + w1.y * r[j+1].y + w1.z * r[j+2].y + w1.w * r[j+3].y;
        o.z += w2.x * r[j].z + w2.y * r[j+1].z + w2.z * r[j+2].z + w2.w * r[j+3].z;
        o.w += w3.x * r[j].w + w3.y * r[j+1].w + w3.z * r[j+2].w + w3.w * r[j+3].w;
        *(float4*)(outbase + (size_t)j * CONVD) = o;
    }
}

// ============================================================
// per-(chunk,head) SSD chunk kernel — tensor-core, batch param
// ============================================================
#define CH_C_HI   0u
#define CH_C_LO   16384u
#define CH_B_HI   32768u
#define CH_B_LO   49152u
#define CH_M_HI   0u
#define CH_M_LO   32768u
#define CH_XT_HI  65536u
#define CH_XT_LO  73728u
#define CH_BTD_HI 81920u
#define CH_BTD_LO 98304u
#define CH_SA     114688u
#define CH_SDS    115200u
#define CH_SMEM   115712u

__global__ __launch_bounds__(256)
void chunk_kernel(int b)
{
    extern __shared__ char smem[];
    float* sA  = (float*)(smem + CH_SA);
    float* sDs = (float*)(smem + CH_SDS);
    const uint32_t sb0 = smem_u32(smem);

    const int tid = threadIdx.x;
    const int wid = tid >> 5, lane = tid & 31;
    const int bid = blockIdx.x;         // 0..2047
    const int h = bid & 31;
    const int c = bid >> 5;
    const size_t m0 = (size_t)b * LSEQ + (size_t)c * CHK;

    // ---- dt = softplus(A_log); inclusive scan of -dt ----
    if (tid < CHK) {
        float alog = g_xbcza[(m0 + tid) * NPROJ + (CONVD + DINNER) + h];
        float dt = alog > 20.f ? alog : log1pf(expf(alog));
        sA[tid] = dt;
    }
    __syncthreads();
    for (int off = 1; off < CHK; off <<= 1) {
        float v = 0.f;
        if (tid < CHK && tid >= off) v = sA[tid - off];
        __syncthreads();
        if (tid < CHK) sA[tid] += v;
        __syncthreads();
    }
    if (tid < CHK) sA[tid] = -sA[tid];
    __syncthreads();
    float aLast = sA[CHK - 1];
    if (tid < CHK) {
        sDs[tid] = __expf(aLast - sA[tid]);
        g_acum[(m0 + tid) * NH + h] = sA[tid];
    }
    if (tid == 0) g_dc[(b * NCH + c) * NH + h] = __expf(aLast);
    __syncthreads();

    // ---- convert C,B -> bf16 hi/lo tiles ----
    for (int u = tid; u < 128 * 16; u += 256) {
        int l = u >> 4, nq = (u & 15) * 4;
        const float* crow = &g_conv[(m0 + l) * CONVD];
        float4 vc = *(const float4*)&crow[DINNER + NH * DST + h * DST + nq];
        float4 vb = *(const float4*)&crow[DINNER + h * DST + nq];
        uint32_t off = SW128((uint32_t)(l * 128 + nq * 2));
        {
            __nv_bfloat16 h0 = __float2bfloat16(vc.x), h1 = __float2bfloat16(vc.y);
            __nv_bfloat16 h2 = __float2bfloat16(vc.z), h3 = __float2bfloat16(vc.w);
            *(uint2*)(smem + CH_C_HI + off) = make_uint2(pack2(h0, h1), pack2(h2, h3));
            __nv_bfloat16 q0 = __float2bfloat16(vc.x - __bfloat162float(h0));
            __nv_bfloat16 q1 = __float2bfloat16(vc.y - __bfloat162float(h1));
            __nv_bfloat16 q2 = __float2bfloat16(vc.z - __bfloat162float(h2));
            __nv_bfloat16 q3 = __float2bfloat16(vc.w - __bfloat162float(h3));
            *(uint2*)(smem + CH_C_LO + off) = make_uint2(pack2(q0, q1), pack2(q2, q3));
        }
        {
            __nv_bfloat16 h0 = __float2bfloat16(vb.x), h1 = __float2bfloat16(vb.y);
            __nv_bfloat16 h2 = __float2bfloat16(vb.z), h3 = __float2bfloat16(vb.w);
            *(uint2*)(smem + CH_B_HI + off) = make_uint2(pack2(h0, h1), pack2(h2, h3));
            __nv_bfloat16 q0 = __float2bfloat16(vb.x - __bfloat162float(h0));
            __nv_bfloat16 q1 = __float2bfloat16(vb.y - __bfloat162float(h1));
            __nv_bfloat16 q2 = __float2bfloat16(vb.z - __bfloat162float(h2));
            __nv_bfloat16 q3 = __float2bfloat16(vb.w - __bfloat162float(h3));
            *(uint2*)(smem + CH_B_LO + off) = make_uint2(pack2(q0, q1), pack2(q2, q3));
        }
    }
    // ---- Btd[n][s] = B[s][n] * ds[s], transposed bf16 hi/lo ----
    for (int u = tid; u < 128 * 16; u += 256) {
        int s = u >> 4, nq = (u & 15) * 4;
        float d = sDs[s];
        float4 v = *(const float4*)&g_conv[(m0 + s) * CONVD + DINNER + h * DST + nq];
        float vv[4] = {v.x * d, v.y * d, v.z * d, v.w * d};
        uint32_t kb = (uint32_t)(s >> 6), cs = (uint32_t)((s & 63) * 2);
#pragma unroll
        for (int j = 0; j < 4; j++) {
            __nv_bfloat16 hh = __float2bfloat16(vv[j]);
            __nv_bfloat16 ll = __float2bfloat16(vv[j] - __bfloat162float(hh));
            uint32_t off = SW128((uint32_t)((nq + j) * 128) + cs);
            *(__nv_bfloat16*)(smem + CH_BTD_HI + kb * 8192 + off) = hh;
            *(__nv_bfloat16*)(smem + CH_BTD_LO + kb * 8192 + off) = ll;
        }
    }
    // ---- Xt[p][s] = X[s][p], transposed bf16 hi/lo ----
    for (int u = tid; u < 128 * 8; u += 256) {
        int s = u >> 3, pq = (u & 7) * 4;
        float4 v = *(const float4*)&g_conv[(m0 + s) * CONVD + h * HDIM + pq];
        float vv[4] = {v.x, v.y, v.z, v.w};
        uint32_t kb = (uint32_t)(s >> 6), cs = (uint32_t)((s & 63) * 2);
#pragma unroll
        for (int j = 0; j < 4; j++) {
            __nv_bfloat16 hh = __float2bfloat16(vv[j]);
            __nv_bfloat16 ll = __float2bfloat16(vv[j] - __bfloat162float(hh));
            uint32_t off = SW128((uint32_t)((pq + j) * 128) + cs);
            *(__nv_bfloat16*)(smem + CH_XT_HI + kb * 4096 + off) = hh;
            *(__nv_bfloat16*)(smem + CH_XT_LO + kb * 4096 + off) = ll;
        }
    }
    __syncthreads();

    const int lrow = lane & 15, lcol = lane >> 4;
    const int gr = lane >> 2, gc = (lane & 3) * 2;

    // ---- phase 1: G = C.B^T (3-term split), warp grid 2x4, K=64 ----
    const int wm = (wid >> 2) * 64;
    const int wn = (wid & 3) * 32;
    float acc[4][4][4];
#pragma unroll
    for (int mi = 0; mi < 4; mi++)
#pragma unroll
        for (int ni = 0; ni < 4; ni++)
#pragma unroll
            for (int r = 0; r < 4; r++) acc[mi][ni][r] = 0.f;

    if (!(wm == 0 && wn >= 64)) {
#pragma unroll
        for (int pt = 0; pt < 3; pt++) {
            uint32_t Ab = sb0 + ((pt == 1) ? CH_C_LO : CH_C_HI);
            uint32_t Bb = sb0 + ((pt == 2) ? CH_B_LO : CH_B_HI);
#pragma unroll
            for (int ks = 0; ks < 4; ks++) {
                uint32_t a[4][4], bb[2][4];
#pragma unroll
                for (int mi = 0; mi < 4; mi++)
                    ldsm4(a[mi], Ab + SW128((wm + mi * 16 + lrow) * 128 + (ks * 2 + lcol) * 16));
#pragma unroll
                for (int bi = 0; bi < 2; bi++)
                    ldsm4(bb[bi], Bb + SW128((wn + bi * 16 + lrow) * 128 + (ks * 2 + lcol) * 16));
#pragma unroll
                for (int mi = 0; mi < 4; mi++)
#pragma unroll
                    for (int ni = 0; ni < 4; ni++) {
                        int bi = ni >> 1, hf = ni & 1;
                        mma16816(acc[mi][ni], a[mi], bb[bi][hf], bb[bi][2 + hf]);
                    }
            }
        }
    }
    __syncthreads();

    // ---- epilogue: decay+mask, split M -> smem ----
#pragma unroll
    for (int ni = 0; ni < 4; ni++) {
        int s0 = wn + ni * 8;
        float aref = sA[s0];
        int sa = s0 + gc, sb = s0 + gc + 1;
        float es0 = __expf(aref - sA[sa]);
        float es1 = __expf(aref - sA[sb]);
        uint32_t kb = (uint32_t)(s0 >> 6);
        uint32_t cbyte = (uint32_t)(((s0 & 63) + gc) * 2);
#pragma unroll
        for (int mi = 0; mi < 4; mi++) {
#pragma unroll
            for (int half = 0; half < 2; half++) {
                int l = wm + mi * 16 + gr + half * 8;
                float el = __expf(sA[l] - aref);
                float v0 = (l >= sa) ? acc[mi][ni][half * 2 + 0] * el * es0 : 0.f;
                float v1 = (l >= sb) ? acc[mi][ni][half * 2 + 1] * el * es1 : 0.f;
                __nv_bfloat16 h0 = __float2bfloat16(v0), h1 = __float2bfloat16(v1);
                __nv_bfloat16 q0 = __float2bfloat16(v0 - __bfloat162float(h0));
                __nv_bfloat16 q1 = __float2bfloat16(v1 - __bfloat162float(h1));
                uint32_t off = SW128((uint32_t)(l * 128) + cbyte);
                *(uint32_t*)(smem + CH_M_HI + kb * 16384 + off) = pack2(h0, h1);
                *(uint32_t*)(smem + CH_M_LO + kb * 16384 + off) = pack2(q0, q1);
            }
        }
    }
    __syncthreads();

    // ---- phase 2: Y_diag = M @ X ----
    {
        const int l16 = wid * 16;
        float y2[4][4];
#pragma unroll
        for (int ni = 0; ni < 4; ni++)
#pragma unroll
            for (int r = 0; r < 4; r++) y2[ni][r] = 0.f;
#pragma unroll
        for (int pt = 0; pt < 3; pt++) {
            uint32_t Ab = sb0 + ((pt == 1) ? CH_M_LO : CH_M_HI);
            uint32_t Bb = sb0 + ((pt == 2) ? CH_XT_LO : CH_XT_HI);
#pragma unroll
            for (int kb = 0; kb < 2; kb++) {
                uint32_t Abuf = Ab + kb * 16384u;
                uint32_t Bbuf = Bb + kb * 4096u;
#pragma unroll
                for (int ks = 0; ks < 4; ks++) {
                    uint32_t a[4], bb[2][4];
                    ldsm4(a, Abuf + SW128((l16 + lrow) * 128 + (ks * 2 + lcol) * 16));
                    ldsm4(bb[0], Bbuf + SW128((lrow) * 128 + (ks * 2 + lcol) * 16));
                    ldsm4(bb[1], Bbuf + SW128((16 + lrow) * 128 + (ks * 2 + lcol) * 16));
#pragma unroll
                    for (int ni = 0; ni < 4; ni++) {
                        int bi = ni >> 1, hf = ni & 1;
                        mma16816(y2[ni], a, bb[bi][hf], bb[bi][2 + hf]);
                    }
                }
            }
        }
#pragma unroll
        for (int ni = 0; ni < 4; ni++) {
            int p = ni * 8 + gc;
            int l = l16 + gr;
            *(float2*)&g_y[(m0 + l) * DINNER + h * HDIM + p] =
                make_float2(y2[ni][0], y2[ni][1]);
            *(float2*)&g_y[(m0 + l + 8) * DINNER + h * HDIM + p] =
                make_float2(y2[ni][2], y2[ni][3]);
        }
    }

    // ---- phase 3: states = Xt . Btd ----
    {
        const int pm = (wid & 1) * 16;
        const int nn = (wid >> 1) * 16;
        float s3[2][4];
#pragma unroll
        for (int ni = 0; ni < 2; ni++)
#pragma unroll
            for (int r = 0; r < 4; r++) s3[ni][r] = 0.f;
#pragma unroll
        for (int pt = 0; pt < 3; pt++) {
            uint32_t Ab = sb0 + ((pt == 1) ? CH_XT_LO : CH_XT_HI);
            uint32_t Bb = sb0 + ((pt == 2) ? CH_BTD_LO : CH_BTD_HI);
#pragma unroll
            for (int kb = 0; kb < 2; kb++) {
                uint32_t Abuf = Ab + kb * 4096u;
                uint32_t Bbuf = Bb + kb * 8192u;
#pragma unroll
                for (int ks = 0; ks < 4; ks++) {
                    uint32_t a[4], bb[4];
                    ldsm4(a, Abuf + SW128((pm + lrow) * 128 + (ks * 2 + lcol) * 16));
                    ldsm4(bb, Bbuf + SW128((nn + lrow) * 128 + (ks * 2 + lcol) * 16));
                    mma16816(s3[0], a, bb[0], bb[2]);
                    mma16816(s3[1], a, bb[1], bb[3]);
                }
            }
        }
        size_t sbase = ((size_t)((b * NCH + c) * NH + h)) * (HDIM * DST);
#pragma unroll
        for (int ni = 0; ni < 2; ni++) {
            int n = nn + ni * 8 + gc;
            int p0 = pm + gr;
            *(float2*)&g_states[sbase + (size_t)p0 * DST + n] =
                make_float2(s3[ni][0], s3[ni][1]);
            *(float2*)&g_states[sbase + (size_t)(p0 + 8) * DST + n] =
                make_float2(s3[ni][2], s3[ni][3]);
        }
    }
}

// ============================================================
// inter-chunk state scan (per batch)
// ============================================================
__global__ __launch_bounds__(512)
void scan_kernel(int b)
{
    int h = blockIdx.x;
    int tid = threadIdx.x;
    float4 S = make_float4(0.f, 0.f, 0.f, 0.f);
    for (int c = 0; c < NCH; c++) {
        size_t base = ((size_t)((b * NCH + c) * NH + h)) * (HDIM * DST);
        float4 stv = *(const float4*)&g_states[base + tid * 4];
        *(float4*)&g_prevs[base + tid * 4] = S;
        float d = g_dc[(b * NCH + c) * NH + h];
        S.x = S.x * d + stv.x;
        S.y = S.y * d + stv.y;
        S.z = S.z * d + stv.z;
        S.w = S.w * d + stv.w;
    }
}

// ============================================================
// Y_off + D*x skip + SiLU gating -> g_yS [hi|lo]  (per batch)
// ============================================================
__global__ __launch_bounds__(256)
void yoff_kernel(int b, const float* __restrict__ Dvec, const float* __restrict__ z_bias)
{
    extern __shared__ float sm[];
    float* Cs = sm;            // [128][68]
    float* Pv = sm + 128*68;   // [32][68]
    float* eA = sm + 128*68 + 32*68;  // [128]

    const int tid = threadIdx.x;
    const int bid = blockIdx.x;     // 0..2047
    const int h = bid & 31;
    const int c = bid >> 5;
    const size_t m0 = (size_t)b * LSEQ + (size_t)c * CHK;
    const size_t pbase = ((size_t)((b * NCH + c) * NH + h)) * (HDIM * DST);

    for (int i = tid; i < CHK * DST; i += 256) {
        int l = i >> 6, n = i & 63;
        Cs[l * 68 + n] = g_conv[(m0 + l) * CONVD + DINNER + NH * DST + h * DST + n];
    }
    for (int i = tid; i < HDIM * DST; i += 256) {
        int p = i >> 6, n = i & 63;
        Pv[p * 68 + n] = g_prevs[pbase + i];
    }
    if (tid < CHK)
        eA[tid] = __expf(g_acum[(m0 + tid) * NH + h]);
    __syncthreads();

    const int p = tid & 31, lg = tid >> 5;
    float4 vp[16];
#pragma unroll
    for (int q = 0; q < 16; q++)
        vp[q] = *(float4*)&Pv[p * 68 + q * 4];
    const float Dh = Dvec[h];
    const int col = h * HDIM + p;
    const float zb = z_bias[col];

#pragma unroll 4
    for (int li = 0; li < 16; li++) {
        int l = lg * 16 + li;
        float acc = 0.f;
#pragma unroll
        for (int q = 0; q < 16; q++) {
            float4 c4 = *(float4*)&Cs[l * 68 + q * 4];
            acc += c4.x * vp[q].x + c4.y * vp[q].y + c4.z * vp[q].z + c4.w * vp[q].w;
        }
        size_t mr = m0 + l;
        float xv = g_conv[mr * CONVD + h * HDIM + p];
        float yv = g_y[mr * DINNER + col] + eA[l] * acc + Dh * xv;
        float zz = g_xbcza[mr * NPROJ + CONVD + col] + zb;
        float sg = 1.f / (1.f + __expf(-zz));
        float gv = yv * (zz * sg);
        __nv_bfloat16 hi = __float2bfloat16(gv);
        __nv_bfloat16 lo = __float2bfloat16(gv - __bfloat162float(hi));
        __nv_bfloat16* yr = g_yS + mr * (size_t)K2;
        yr[col] = hi; yr[1024 + col] = lo;
    }
}

// ============================================================
// launch — batch-pipelined with a forked capture stream
// ============================================================
extern "C" void kernel_launch(void* const* d_in, const int* in_sizes, int n_in,
                              void* d_out, int out_size)
{
    (void)in_sizes; (void)n_in; (void)out_size;
    const float* u      = (const float*)d_in[0];
    const float* W_in   = (const float*)d_in[1];
    const float* conv_w = (const float*)d_in[2];
    const float* conv_b = (const float*)d_in[3];
    const float* z_bias = (const float*)d_in[4];
    const float* Dv     = (const float*)d_in[5];
    const float* W_out  = (const float*)d_in[6];
    float* out = (float*)d_out;

    float *p_xbcza = nullptr;
    __nv_bfloat16 *p_uS = nullptr, *p_WinS = nullptr, *p_yS = nullptr, *p_WoutS = nullptr;
    cudaGetSymbolAddress((void**)&p_xbcza, g_xbcza);
    cudaGetSymbolAddress((void**)&p_uS, g_uS);
    cudaGetSymbolAddress((void**)&p_WinS, g_WinS);
    cudaGetSymbolAddress((void**)&p_yS, g_yS);
    cudaGetSymbolAddress((void**)&p_WoutS, g_WoutS);

    static cudaStream_t sB = nullptr;
    static cudaEvent_t evG1b0 = nullptr, evB = nullptr;
    if (!sB) {
        cudaStreamCreateWithFlags(&sB, cudaStreamNonBlocking);
        cudaEventCreateWithFlags(&evG1b0, cudaEventDisableTiming);
        cudaEventCreateWithFlags(&evB, cudaEventDisableTiming);
    }

    static const size_t GEMM_SMEM = NSTAGE * 32768;  // 96 KB
    static const size_t YOFF_SMEM = (128 * 68 + 32 * 68 + 128) * sizeof(float);
    cudaFuncSetAttribute(gemm_mma, cudaFuncAttributeMaxDynamicSharedMemorySize, (int)GEMM_SMEM);
    cudaFuncSetAttribute(chunk_kernel, cudaFuncAttributeMaxDynamicSharedMemorySize, CH_SMEM);
    cudaFuncSetAttribute(yoff_kernel,  cudaFuncAttributeMaxDynamicSharedMemorySize, (int)YOFF_SMEM);

    const dim3 g1grid((NPROJ + BN - 1) / BN, LSEQ / BM);   // (49, 64) per batch
    const dim3 g2grid(1024 / BN, LSEQ / BM);               // (8, 64) per batch
    const dim3 cvgrid(CONVD / 1024, LSEQ / 4);             // (5, 2048) per batch

    // ---- stage 0 (stream 0): splits (W_out early so both G2s can use it) ----
    split2<<<MROWS * 2, 256>>>(u, p_uS);
    split2<<<NPROJ * 2, 256>>>(W_in, p_WinS);
    split2<<<1024 * 2, 256>>>(W_out, p_WoutS);

    // ---- G1 batch 0, then fork ----
    gemm_mma<<<g1grid, 256, GEMM_SMEM>>>(p_xbcza, p_uS, p_WinS, NPROJ, NPROJ, 0);
    cudaEventRecord(evG1b0, 0);

    // ---- stream 0: G1 batch 1 ----
    gemm_mma<<<g1grid, 256, GEMM_SMEM>>>(p_xbcza, p_uS, p_WinS, NPROJ, NPROJ, LSEQ);

    // ---- stream B: full batch-0 tail, concurrent with G1(b1) ----
    cudaStreamWaitEvent(sB, evG1b0, 0);
    conv_kernel<<<cvgrid, 256, 0, sB>>>(conv_w, conv_b, 0);
    chunk_kernel<<<NCH * NH, 256, CH_SMEM, sB>>>(0);
    scan_kernel<<<NH, 512, 0, sB>>>(0);
    yoff_kernel<<<NCH * NH, 256, YOFF_SMEM, sB>>>(0, Dv, z_bias);
    gemm_mma<<<g2grid, 256, GEMM_SMEM, sB>>>(out, p_yS, p_WoutS, 1024, 1024, 0);
    cudaEventRecord(evB, sB);

    // ---- stream 0: batch-1 tail ----
    conv_kernel<<<cvgrid, 256>>>(conv_w, conv_b, LSEQ);
    chunk_kernel<<<NCH * NH, 256, CH_SMEM>>>(1);
    scan_kernel<<<NH, 512>>>(1);
    yoff_kernel<<<NCH * NH, 256, YOFF_SMEM>>>(1, Dv, z_bias);
    gemm_mma<<<g2grid, 256, GEMM_SMEM>>>(out, p_yS, p_WoutS, 1024, 1024, LSEQ);

    // ---- join ----
    cudaStreamWaitEvent(0, evB, 0);
}

// round 14
// speedup vs baseline: 1.2288x; 1.0542x over previous
#include <cuda_runtime.h>
#include <cuda_bf16.h>
#include <math.h>
#include <stdint.h>

// ---------------- problem constants ----------------
#define BATCH  2
#define LSEQ   8192
#define DMODEL 1024
#define NPROJ  6176
#define CONVD  5120
#define DINNER 1024
#define NH     32
#define DST    64
#define HDIM   32
#define CHK    128
#define NCH    64
#define MROWS  (BATCH*LSEQ)   // 16384

// split-bf16 GEMM constants
#define K2     2048            // stored: [hi | lo]
#define BM     128
#define BN     128
#define BK     64
#define NSTAGE 3
#define NCHUNK 48              // logical K = 3072

// pipeline slicing
#define NSLICE 4
#define SLROWS (LSEQ / NSLICE)     // 2048
#define SLCHK  (SLROWS / CHK)      // 16

// ---------------- scratch (device globals) --------
__device__ float g_xbcza[(size_t)MROWS * NPROJ];
__device__ float g_conv [(size_t)MROWS * CONVD];
__device__ float g_acum [(size_t)MROWS * NH];
__device__ float g_y    [(size_t)MROWS * DINNER];
__device__ float g_states[(size_t)BATCH*NCH*NH*HDIM*DST];
__device__ float g_prevs [(size_t)BATCH*NCH*NH*HDIM*DST];
__device__ float g_dc   [BATCH*NCH*NH];

__device__ __nv_bfloat16 g_uS   [(size_t)MROWS * K2];
__device__ __nv_bfloat16 g_WinS [(size_t)NPROJ * K2 + 1024];
__device__ __nv_bfloat16 g_yS   [(size_t)MROWS * K2];
__device__ __nv_bfloat16 g_WoutS[(size_t)1024 * K2];

// ---------------- helpers ----------------
__device__ __forceinline__ uint32_t smem_u32(const void* p) {
    uint32_t a;
    asm("{ .reg .u64 t; cvta.to.shared.u64 t, %1; cvt.u32.u64 %0, t; }"
        : "=r"(a) : "l"(p));
    return a;
}
#define SW128(o) ((o) ^ (((o) >> 3) & 0x70))

__device__ __forceinline__ void ldsm4(uint32_t* r, uint32_t addr) {
    asm volatile("ldmatrix.sync.aligned.m8n8.x4.shared.b16 {%0,%1,%2,%3}, [%4];"
        : "=r"(r[0]), "=r"(r[1]), "=r"(r[2]), "=r"(r[3]) : "r"(addr));
}
__device__ __forceinline__ void mma16816(float* c, const uint32_t* a,
                                         uint32_t b0, uint32_t b1) {
    asm volatile(
        "mma.sync.aligned.m16n8k16.row.col.f32.bf16.bf16.f32 "
        "{%0,%1,%2,%3}, {%4,%5,%6,%7}, {%8,%9}, {%0,%1,%2,%3};"
        : "+f"(c[0]), "+f"(c[1]), "+f"(c[2]), "+f"(c[3])
        : "r"(a[0]), "r"(a[1]), "r"(a[2]), "r"(a[3]), "r"(b0), "r"(b1));
}
__device__ __forceinline__ uint32_t pack2(__nv_bfloat16 a, __nv_bfloat16 b) {
    return (uint32_t)__bfloat16_as_ushort(a) | ((uint32_t)__bfloat16_as_ushort(b) << 16);
}

// ============================================================
// split kernel: fp32 [M,1024] -> bf16 [M,2048] as [hi|lo]
// ============================================================
__global__ __launch_bounds__(256)
void split2(const float* __restrict__ X, __nv_bfloat16* __restrict__ Y)
{
    size_t idx = (size_t)blockIdx.x * 256 + threadIdx.x;
    size_t m = idx >> 9;
    int k2 = (int)(idx & 511) * 2;
    float2 x = *(const float2*)&X[m * 1024 + k2];
    __nv_bfloat16 h0 = __float2bfloat16(x.x);
    __nv_bfloat16 h1 = __float2bfloat16(x.y);
    __nv_bfloat16 l0 = __float2bfloat16(x.x - __bfloat162float(h0));
    __nv_bfloat16 l1 = __float2bfloat16(x.y - __bfloat162float(h1));
    __nv_bfloat162 hi; hi.x = h0; hi.y = h1;
    __nv_bfloat162 lo; lo.x = l0; lo.y = l1;
    __nv_bfloat16* row = Y + m * (size_t)K2;
    *(__nv_bfloat162*)&row[k2]        = hi;
    *(__nv_bfloat162*)&row[1024 + k2] = lo;
}

// ============================================================
// bf16 warp-MMA GEMM, m_base offset
// ============================================================
__global__ __launch_bounds__(256, 2)
void gemm_mma(float* __restrict__ C,
              const __nv_bfloat16* __restrict__ A,
              const __nv_bfloat16* __restrict__ B,
              int N_out, int ldc, int m_base)
{
    extern __shared__ char smem[];
    const int tid  = threadIdx.x;
    const int wid  = tid >> 5;
    const int lane = tid & 31;
    const int m0 = m_base + blockIdx.y * BM;
    const int n0 = blockIdx.x * BN;
    const int wm = (wid >> 2) * 64;
    const int wn = (wid & 3) * 32;

    char* tiles = smem;

    auto fill = [&](int chunk) {
        int s = chunk % NSTAGE;
        int part = chunk >> 4;
        int ko = (chunk & 15) * BK;
        int aoff = (part == 1) ? 1024 : 0;
        int boff = (part == 2) ? 1024 : 0;
        char* As = tiles + s * 32768;
        char* Bs = As + 16384;
        const char* Ag = (const char*)(A + (size_t)m0 * K2 + aoff + ko);
        const char* Bg = (const char*)(B + (size_t)n0 * K2 + boff + ko);
        uint32_t Asb = smem_u32(As), Bsb = smem_u32(Bs);
#pragma unroll
        for (int r = 0; r < 4; r++) {
            int cid = tid + r * 256;
            int row = cid >> 3, col = cid & 7;
            uint32_t dst = Asb + SW128(row * 128 + col * 16);
            const void* src = Ag + (size_t)row * (K2 * 2) + col * 16;
            asm volatile("cp.async.cg.shared.global [%0], [%1], 16;" :: "r"(dst), "l"(src));
        }
#pragma unroll
        for (int r = 0; r < 4; r++) {
            int cid = tid + r * 256;
            int row = cid >> 3, col = cid & 7;
            uint32_t dst = Bsb + SW128(row * 128 + col * 16);
            const void* src = Bg + (size_t)row * (K2 * 2) + col * 16;
            asm volatile("cp.async.cg.shared.global [%0], [%1], 16;" :: "r"(dst), "l"(src));
        }
        asm volatile("cp.async.commit_group;" ::: "memory");
    };

    float acc[4][4][4];
#pragma unroll
    for (int mi = 0; mi < 4; mi++)
#pragma unroll
        for (int ni = 0; ni < 4; ni++)
#pragma unroll
            for (int r = 0; r < 4; r++) acc[mi][ni][r] = 0.f;

    fill(0); fill(1);

    const int lrow = lane & 15;
    const int lcol = lane >> 4;

    for (int i = 0; i < NCHUNK; i++) {
        int s = i % NSTAGE;
        if (i + 1 < NCHUNK)
            asm volatile("cp.async.wait_group 1;" ::: "memory");
        else
            asm volatile("cp.async.wait_group 0;" ::: "memory");
        __syncthreads();

        if (i + 2 < NCHUNK) fill(i + 2);

        uint32_t Asb = smem_u32(tiles + s * 32768);
        uint32_t Bsb = Asb + 16384;

#pragma unroll
        for (int ks = 0; ks < 4; ks++) {
            uint32_t a[4][4], b[2][4];
#pragma unroll
            for (int mi = 0; mi < 4; mi++)
                ldsm4(a[mi], Asb + SW128((wm + mi * 16 + lrow) * 128 + (ks * 2 + lcol) * 16));
#pragma unroll
            for (int bi = 0; bi < 2; bi++)
                ldsm4(b[bi], Bsb + SW128((wn + bi * 16 + lrow) * 128 + (ks * 2 + lcol) * 16));
#pragma unroll
            for (int mi = 0; mi < 4; mi++)
#pragma unroll
                for (int ni = 0; ni < 4; ni++) {
                    int bi = ni >> 1, hf = ni & 1;
                    mma16816(acc[mi][ni], a[mi], b[bi][hf], b[bi][2 + hf]);
                }
        }
    }

    const int gr = lane >> 2;
    const int gc = (lane & 3) * 2;
#pragma unroll
    for (int mi = 0; mi < 4; mi++) {
        int m = m0 + wm + mi * 16 + gr;
#pragma unroll
        for (int ni = 0; ni < 4; ni++) {
            int n = n0 + wn + ni * 8 + gc;
            if (n < N_out) {
                float2 v0 = make_float2(acc[mi][ni][0], acc[mi][ni][1]);
                float2 v1 = make_float2(acc[mi][ni][2], acc[mi][ni][3]);
                *(float2*)&C[(size_t)m * ldc + n]       = v0;
                *(float2*)&C[(size_t)(m + 8) * ldc + n] = v1;
            }
        }
    }
}

// ============================================================
// depthwise causal conv (register-blocked 4ch x 4t), m_base offset
// ============================================================
__global__ __launch_bounds__(256)
void conv_kernel(const float* __restrict__ cw, const float* __restrict__ cb, int m_base)
{
    int c4 = blockIdx.x * 256 + threadIdx.x;
    int ch = c4 * 4;
    int m0 = m_base + blockIdx.y * 4;
    int t0 = m0 & (LSEQ - 1);

    const float4* wp = (const float4*)(cw + ch * 4);
    float4 w0 = wp[0], w1 = wp[1], w2 = wp[2], w3 = wp[3];
    float4 bias = *(const float4*)(cb + ch);

    float4 r[7];
    const float* base = g_xbcza + (size_t)m0 * NPROJ + ch;
#pragma unroll
    for (int k = 0; k < 7; k++) {
        int tt = t0 - 3 + k;
        if (tt >= 0)
            r[k] = *(const float4*)(base + (long)(k - 3) * NPROJ);
        else
            r[k] = make_float4(0.f, 0.f, 0.f, 0.f);
    }

    float* outbase = g_conv + (size_t)m0 * CONVD + ch;
#pragma unroll
    for (int j = 0; j < 4; j++) {
        float4 o = bias;
        o.x += w0.x * r[j].x + w0.y * r[j+1].x + w0.z * r[j+2].x + w0.w * r[j+3].x;
        o.y += w1.x * r[j].y + w1.y * r[j+1].y + w1.z * r[j+2].y + w1.w * r[j+3].y;
        o.z += w2.x * r[j].z + w2.y * r[j+1].z + w2.z * r[j+2].z + w2.w * r[j+3].z;
        o.w += w3.x * r[j].w + w3.y * r[j+1].w + w3.z * r[j+2].w + w3.w * r[j+3].w;
        *(float4*)(outbase + (size_t)j * CONVD) = o;
    }
}

// ============================================================
// per-(chunk,head) SSD chunk kernel — tensor-core, 81KB smem (2 CTA/SM)
// ============================================================
#define CB_C_HI   0u
#define CB_C_LO   16384u
#define CB_B_HI   32768u
#define CB_B_LO   49152u
#define CB_M_HI   0u
#define CB_M_LO   32768u
#define CB_XT_HI  65536u
#define CB_XT_LO  73728u
#define CB_BTD_HI 0u
#define CB_BTD_LO 16384u
#define CB_SA     81920u
#define CB_SDS    82432u
#define CB_SMEM   82944u

__global__ __launch_bounds__(256, 2)
void chunk_kernel(int b, int c0)
{
    extern __shared__ char smem[];
    float* sA  = (float*)(smem + CB_SA);
    float* sDs = (float*)(smem + CB_SDS);
    const uint32_t sb0 = smem_u32(smem);

    const int tid = threadIdx.x;
    const int wid = tid >> 5, lane = tid & 31;
    const int bid = blockIdx.x;
    const int h = bid & 31;
    const int c = c0 + (bid >> 5);
    const size_t m0 = (size_t)b * LSEQ + (size_t)c * CHK;

    // ---- dt = softplus(A_log); inclusive scan of -dt ----
    if (tid < CHK) {
        float alog = g_xbcza[(m0 + tid) * NPROJ + (CONVD + DINNER) + h];
        float dt = alog > 20.f ? alog : log1pf(expf(alog));
        sA[tid] = dt;
    }
    __syncthreads();
    for (int off = 1; off < CHK; off <<= 1) {
        float v = 0.f;
        if (tid < CHK && tid >= off) v = sA[tid - off];
        __syncthreads();
        if (tid < CHK) sA[tid] += v;
        __syncthreads();
    }
    if (tid < CHK) sA[tid] = -sA[tid];
    __syncthreads();
    float aLast = sA[CHK - 1];
    if (tid < CHK) {
        sDs[tid] = __expf(aLast - sA[tid]);
        g_acum[(m0 + tid) * NH + h] = sA[tid];
    }
    if (tid == 0) g_dc[(b * NCH + c) * NH + h] = __expf(aLast);
    __syncthreads();

    // ---- convert C,B -> bf16 hi/lo tiles ----
    for (int u = tid; u < 128 * 16; u += 256) {
        int l = u >> 4, nq = (u & 15) * 4;
        const float* crow = &g_conv[(m0 + l) * CONVD];
        float4 vc = *(const float4*)&crow[DINNER + NH * DST + h * DST + nq];
        float4 vb = *(const float4*)&crow[DINNER + h * DST + nq];
        uint32_t off = SW128((uint32_t)(l * 128 + nq * 2));
        {
            __nv_bfloat16 h0 = __float2bfloat16(vc.x), h1 = __float2bfloat16(vc.y);
            __nv_bfloat16 h2 = __float2bfloat16(vc.z), h3 = __float2bfloat16(vc.w);
            *(uint2*)(smem + CB_C_HI + off) = make_uint2(pack2(h0, h1), pack2(h2, h3));
            __nv_bfloat16 q0 = __float2bfloat16(vc.x - __bfloat162float(h0));
            __nv_bfloat16 q1 = __float2bfloat16(vc.y - __bfloat162float(h1));
            __nv_bfloat16 q2 = __float2bfloat16(vc.z - __bfloat162float(h2));
            __nv_bfloat16 q3 = __float2bfloat16(vc.w - __bfloat162float(h3));
            *(uint2*)(smem + CB_C_LO + off) = make_uint2(pack2(q0, q1), pack2(q2, q3));
        }
        {
            __nv_bfloat16 h0 = __float2bfloat16(vb.x), h1 = __float2bfloat16(vb.y);
            __nv_bfloat16 h2 = __float2bfloat16(vb.z), h3 = __float2bfloat16(vb.w);
            *(uint2*)(smem + CB_B_HI + off) = make_uint2(pack2(h0, h1), pack2(h2, h3));
            __nv_bfloat16 q0 = __float2bfloat16(vb.x - __bfloat162float(h0));
            __nv_bfloat16 q1 = __float2bfloat16(vb.y - __bfloat162float(h1));
            __nv_bfloat16 q2 = __float2bfloat16(vb.z - __bfloat162float(h2));
            __nv_bfloat16 q3 = __float2bfloat16(vb.w - __bfloat162float(h3));
            *(uint2*)(smem + CB_B_LO + off) = make_uint2(pack2(q0, q1), pack2(q2, q3));
        }
    }
    // ---- Xt[p][s] = X[s][p], transposed bf16 hi/lo ----
    for (int u = tid; u < 128 * 8; u += 256) {
        int s = u >> 3, pq = (u & 7) * 4;
        float4 v = *(const float4*)&g_conv[(m0 + s) * CONVD + h * HDIM + pq];
        float vv[4] = {v.x, v.y, v.z, v.w};
        uint32_t kb = (uint32_t)(s >> 6), cs = (uint32_t)((s & 63) * 2);
#pragma unroll
        for (int j = 0; j < 4; j++) {
            __nv_bfloat16 hh = __float2bfloat16(vv[j]);
            __nv_bfloat16 ll = __float2bfloat16(vv[j] - __bfloat162float(hh));
            uint32_t off = SW128((uint32_t)((pq + j) * 128) + cs);
            *(__nv_bfloat16*)(smem + CB_XT_HI + kb * 4096 + off) = hh;
            *(__nv_bfloat16*)(smem + CB_XT_LO + kb * 4096 + off) = ll;
        }
    }
    __syncthreads();

    const int lrow = lane & 15, lcol = lane >> 4;
    const int gr = lane >> 2, gc = (lane & 3) * 2;

    // ---- phase 1: G = C.B^T (3-term split), warp grid 2x4, K=64 ----
    const int wm = (wid >> 2) * 64;
    const int wn = (wid & 3) * 32;
    float acc[4][4][4];
#pragma unroll
    for (int mi = 0; mi < 4; mi++)
#pragma unroll
        for (int ni = 0; ni < 4; ni++)
#pragma unroll
            for (int r = 0; r < 4; r++) acc[mi][ni][r] = 0.f;

    if (!(wm == 0 && wn >= 64)) {
#pragma unroll
        for (int pt = 0; pt < 3; pt++) {
            uint32_t Ab = sb0 + ((pt == 1) ? CB_C_LO : CB_C_HI);
            uint32_t Bb = sb0 + ((pt == 2) ? CB_B_LO : CB_B_HI);
#pragma unroll
            for (int ks = 0; ks < 4; ks++) {
                uint32_t a[4][4], bb[2][4];
#pragma unroll
                for (int mi = 0; mi < 4; mi++)
                    ldsm4(a[mi], Ab + SW128((wm + mi * 16 + lrow) * 128 + (ks * 2 + lcol) * 16));
#pragma unroll
                for (int bi = 0; bi < 2; bi++)
                    ldsm4(bb[bi], Bb + SW128((wn + bi * 16 + lrow) * 128 + (ks * 2 + lcol) * 16));
#pragma unroll
                for (int mi = 0; mi < 4; mi++)
#pragma unroll
                    for (int ni = 0; ni < 4; ni++) {
                        int bi = ni >> 1, hf = ni & 1;
                        mma16816(acc[mi][ni], a[mi], bb[bi][hf], bb[bi][2 + hf]);
                    }
            }
        }
    }
    __syncthreads();

    // ---- epilogue: decay+mask, split M -> smem (overlay C/B) ----
#pragma unroll
    for (int ni = 0; ni < 4; ni++) {
        int s0 = wn + ni * 8;
        float aref = sA[s0];
        int sa = s0 + gc, sb = s0 + gc + 1;
        float es0 = __expf(aref - sA[sa]);
        float es1 = __expf(aref - sA[sb]);
        uint32_t kb = (uint32_t)(s0 >> 6);
        uint32_t cbyte = (uint32_t)(((s0 & 63) + gc) * 2);
#pragma unroll
        for (int mi = 0; mi < 4; mi++) {
#pragma unroll
            for (int half = 0; half < 2; half++) {
                int l = wm + mi * 16 + gr + half * 8;
                float el = __expf(sA[l] - aref);
                float v0 = (l >= sa) ? acc[mi][ni][half * 2 + 0] * el * es0 : 0.f;
                float v1 = (l >= sb) ? acc[mi][ni][half * 2 + 1] * el * es1 : 0.f;
                __nv_bfloat16 h0 = __float2bfloat16(v0), h1 = __float2bfloat16(v1);
                __nv_bfloat16 q0 = __float2bfloat16(v0 - __bfloat162float(h0));
                __nv_bfloat16 q1 = __float2bfloat16(v1 - __bfloat162float(h1));
                uint32_t off = SW128((uint32_t)(l * 128) + cbyte);
                *(uint32_t*)(smem + CB_M_HI + kb * 16384 + off) = pack2(h0, h1);
                *(uint32_t*)(smem + CB_M_LO + kb * 16384 + off) = pack2(q0, q1);
            }
        }
    }
    __syncthreads();

    // ---- phase 2: Y_diag = M @ X ----
    {
        const int l16 = wid * 16;
        float y2[4][4];
#pragma unroll
        for (int ni = 0; ni < 4; ni++)
#pragma unroll
            for (int r = 0; r < 4; r++) y2[ni][r] = 0.f;
#pragma unroll
        for (int pt = 0; pt < 3; pt++) {
            uint32_t Ab = sb0 + ((pt == 1) ? CB_M_LO : CB_M_HI);
            uint32_t Bb = sb0 + ((pt == 2) ? CB_XT_LO : CB_XT_HI);
#pragma unroll
            for (int kb = 0; kb < 2; kb++) {
                uint32_t Abuf = Ab + kb * 16384u;
                uint32_t Bbuf = Bb + kb * 4096u;
#pragma unroll
                for (int ks = 0; ks < 4; ks++) {
                    uint32_t a[4], bb[2][4];
                    ldsm4(a, Abuf + SW128((l16 + lrow) * 128 + (ks * 2 + lcol) * 16));
                    ldsm4(bb[0], Bbuf + SW128((lrow) * 128 + (ks * 2 + lcol) * 16));
                    ldsm4(bb[1], Bbuf + SW128((16 + lrow) * 128 + (ks * 2 + lcol) * 16));
#pragma unroll
                    for (int ni = 0; ni < 4; ni++) {
                        int bi = ni >> 1, hf = ni & 1;
                        mma16816(y2[ni], a, bb[bi][hf], bb[bi][2 + hf]);
                    }
                }
            }
        }
#pragma unroll
        for (int ni = 0; ni < 4; ni++) {
            int p = ni * 8 + gc;
            int l = l16 + gr;
            *(float2*)&g_y[(m0 + l) * DINNER + h * HDIM + p] =
                make_float2(y2[ni][0], y2[ni][1]);
            *(float2*)&g_y[(m0 + l + 8) * DINNER + h * HDIM + p] =
                make_float2(y2[ni][2], y2[ni][3]);
        }
    }
    __syncthreads();   // all M reads done

    // ---- build Btd[n][s] = B[s][n]*ds[s] hi/lo (overlay M area) ----
    for (int u = tid; u < 128 * 16; u += 256) {
        int s = u >> 4, nq = (u & 15) * 4;
        float d = sDs[s];
        float4 v = *(const float4*)&g_conv[(m0 + s) * CONVD + DINNER + h * DST + nq];
        float vv[4] = {v.x * d, v.y * d, v.z * d, v.w * d};
        uint32_t kb = (uint32_t)(s >> 6), cs = (uint32_t)((s & 63) * 2);
#pragma unroll
        for (int j = 0; j < 4; j++) {
            __nv_bfloat16 hh = __float2bfloat16(vv[j]);
            __nv_bfloat16 ll = __float2bfloat16(vv[j] - __bfloat162float(hh));
            uint32_t off = SW128((uint32_t)((nq + j) * 128) + cs);
            *(__nv_bfloat16*)(smem + CB_BTD_HI + kb * 8192 + off) = hh;
            *(__nv_bfloat16*)(smem + CB_BTD_LO + kb * 8192 + off) = ll;
        }
    }
    __syncthreads();

    // ---- phase 3: states = Xt . Btd ----
    {
        const int pm = (wid & 1) * 16;
        const int nn = (wid >> 1) * 16;
        float s3[2][4];
#pragma unroll
        for (int ni = 0; ni < 2; ni++)
#pragma unroll
            for (int r = 0; r < 4; r++) s3[ni][r] = 0.f;
#pragma unroll
        for (int pt = 0; pt < 3; pt++) {
            uint32_t Ab = sb0 + ((pt == 1) ? CB_XT_LO : CB_XT_HI);
            uint32_t Bb = sb0 + ((pt == 2) ? CB_BTD_LO : CB_BTD_HI);
#pragma unroll
            for (int kb = 0; kb < 2; kb++) {
                uint32_t Abuf = Ab + kb * 4096u;
                uint32_t Bbuf = Bb + kb * 8192u;
#pragma unroll
                for (int ks = 0; ks < 4; ks++) {
                    uint32_t a[4], bb[4];
                    ldsm4(a, Abuf + SW128((pm + lrow) * 128 + (ks * 2 + lcol) * 16));
                    ldsm4(bb, Bbuf + SW128((nn + lrow) * 128 + (ks * 2 + lcol) * 16));
                    mma16816(s3[0], a, bb[0], bb[2]);
                    mma16816(s3[1], a, bb[1], bb[3]);
                }
            }
        }
        size_t sbase = ((size_t)((b * NCH + c) * NH + h)) * (HDIM * DST);
#pragma unroll
        for (int ni = 0; ni < 2; ni++) {
            int n = nn + ni * 8 + gc;
            int p0 = pm + gr;
            *(float2*)&g_states[sbase + (size_t)p0 * DST + n] =
                make_float2(s3[ni][0], s3[ni][1]);
            *(float2*)&g_states[sbase + (size_t)(p0 + 8) * DST + n] =
                make_float2(s3[ni][2], s3[ni][3]);
        }
    }
}

// ============================================================
// inter-chunk state scan (per batch)
// ============================================================
__global__ __launch_bounds__(512)
void scan_kernel(int b)
{
    int h = blockIdx.x;
    int tid = threadIdx.x;
    float4 S = make_float4(0.f, 0.f, 0.f, 0.f);
    for (int c = 0; c < NCH; c++) {
        size_t base = ((size_t)((b * NCH + c) * NH + h)) * (HDIM * DST);
        float4 stv = *(const float4*)&g_states[base + tid * 4];
        *(float4*)&g_prevs[base + tid * 4] = S;
        float d = g_dc[(b * NCH + c) * NH + h];
        S.x = S.x * d + stv.x;
        S.y = S.y * d + stv.y;
        S.z = S.z * d + stv.z;
        S.w = S.w * d + stv.w;
    }
}

// ============================================================
// Y_off + D*x skip + SiLU gating -> g_yS [hi|lo]  (per batch)
// ============================================================
__global__ __launch_bounds__(256)
void yoff_kernel(int b, const float* __restrict__ Dvec, const float* __restrict__ z_bias)
{
    extern __shared__ float sm[];
    float* Cs = sm;            // [128][68]
    float* Pv = sm + 128*68;   // [32][68]
    float* eA = sm + 128*68 + 32*68;  // [128]

    const int tid = threadIdx.x;
    const int bid = blockIdx.x;
    const int h = bid & 31;
    const int c = bid >> 5;
    const size_t m0 = (size_t)b * LSEQ + (size_t)c * CHK;
    const size_t pbase = ((size_t)((b * NCH + c) * NH + h)) * (HDIM * DST);

    for (int i = tid; i < CHK * DST; i += 256) {
        int l = i >> 6, n = i & 63;
        Cs[l * 68 + n] = g_conv[(m0 + l) * CONVD + DINNER + NH * DST + h * DST + n];
    }
    for (int i = tid; i < HDIM * DST; i += 256) {
        int p = i >> 6, n = i & 63;
        Pv[p * 68 + n] = g_prevs[pbase + i];
    }
    if (tid < CHK)
        eA[tid] = __expf(g_acum[(m0 + tid) * NH + h]);
    __syncthreads();

    const int p = tid & 31, lg = tid >> 5;
    float4 vp[16];
#pragma unroll
    for (int q = 0; q < 16; q++)
        vp[q] = *(float4*)&Pv[p * 68 + q * 4];
    const float Dh = Dvec[h];
    const int col = h * HDIM + p;
    const float zb = z_bias[col];

#pragma unroll 4
    for (int li = 0; li < 16; li++) {
        int l = lg * 16 + li;
        float acc = 0.f;
#pragma unroll
        for (int q = 0; q < 16; q++) {
            float4 c4 = *(float4*)&Cs[l * 68 + q * 4];
            acc += c4.x * vp[q].x + c4.y * vp[q].y + c4.z * vp[q].z + c4.w * vp[q].w;
        }
        size_t mr = m0 + l;
        float xv = g_conv[mr * CONVD + h * HDIM + p];
        float yv = g_y[mr * DINNER + col] + eA[l] * acc + Dh * xv;
        float zz = g_xbcza[mr * NPROJ + CONVD + col] + zb;
        float sg = 1.f / (1.f + __expf(-zz));
        float gv = yv * (zz * sg);
        __nv_bfloat16 hi = __float2bfloat16(gv);
        __nv_bfloat16 lo = __float2bfloat16(gv - __bfloat162float(hi));
        __nv_bfloat16* yr = g_yS + mr * (size_t)K2;
        yr[col] = hi; yr[1024 + col] = lo;
    }
}

// ============================================================
// launch — slice-pipelined across two streams
// ============================================================
extern "C" void kernel_launch(void* const* d_in, const int* in_sizes, int n_in,
                              void* d_out, int out_size)
{
    (void)in_sizes; (void)n_in; (void)out_size;
    const float* u      = (const float*)d_in[0];
    const float* W_in   = (const float*)d_in[1];
    const float* conv_w = (const float*)d_in[2];
    const float* conv_b = (const float*)d_in[3];
    const float* z_bias = (const float*)d_in[4];
    const float* Dv     = (const float*)d_in[5];
    const float* W_out  = (const float*)d_in[6];
    float* out = (float*)d_out;

    float *p_xbcza = nullptr;
    __nv_bfloat16 *p_uS = nullptr, *p_WinS = nullptr, *p_yS = nullptr, *p_WoutS = nullptr;
    cudaGetSymbolAddress((void**)&p_xbcza, g_xbcza);
    cudaGetSymbolAddress((void**)&p_uS, g_uS);
    cudaGetSymbolAddress((void**)&p_WinS, g_WinS);
    cudaGetSymbolAddress((void**)&p_yS, g_yS);
    cudaGetSymbolAddress((void**)&p_WoutS, g_WoutS);

    static cudaStream_t sB = nullptr;
    static cudaEvent_t evSl[BATCH * NSLICE] = {};
    static cudaEvent_t evB = nullptr;
    if (!sB) {
        cudaStreamCreateWithFlags(&sB, cudaStreamNonBlocking);
        for (int i = 0; i < BATCH * NSLICE; i++)
            cudaEventCreateWithFlags(&evSl[i], cudaEventDisableTiming);
        cudaEventCreateWithFlags(&evB, cudaEventDisableTiming);
    }

    static const size_t GEMM_SMEM = NSTAGE * 32768;  // 96 KB
    static const size_t YOFF_SMEM = (128 * 68 + 32 * 68 + 128) * sizeof(float);
    cudaFuncSetAttribute(gemm_mma, cudaFuncAttributeMaxDynamicSharedMemorySize, (int)GEMM_SMEM);
    cudaFuncSetAttribute(chunk_kernel, cudaFuncAttributeMaxDynamicSharedMemorySize, CB_SMEM);
    cudaFuncSetAttribute(yoff_kernel,  cudaFuncAttributeMaxDynamicSharedMemorySize, (int)YOFF_SMEM);

    const dim3 g1grid((NPROJ + BN - 1) / BN, SLROWS / BM);  // (49, 16) per slice
    const dim3 g2grid(1024 / BN, LSEQ / BM);                // (8, 64) per batch
    const dim3 cvgrid(CONVD / 1024, SLROWS / 4);            // (5, 512) per slice

    // ---- stream 0: splits, then all G1 slices with per-slice events ----
    split2<<<MROWS * 2, 256>>>(u, p_uS);
    split2<<<NPROJ * 2, 256>>>(W_in, p_WinS);
    split2<<<1024 * 2, 256>>>(W_out, p_WoutS);

    for (int i = 0; i < BATCH * NSLICE; i++) {
        int m_base = i * SLROWS;
        gemm_mma<<<g1grid, 256, GEMM_SMEM>>>(p_xbcza, p_uS, p_WinS, NPROJ, NPROJ, m_base);
        cudaEventRecord(evSl[i], 0);
    }

    // ---- stream B: per-slice conv+chunk, then per-batch scan/yoff/G2 ----
    for (int b = 0; b < BATCH; b++) {
        for (int s = 0; s < NSLICE; s++) {
            int i = b * NSLICE + s;
            cudaStreamWaitEvent(sB, evSl[i], 0);
            conv_kernel<<<cvgrid, 256, 0, sB>>>(conv_w, conv_b, i * SLROWS);
            chunk_kernel<<<SLCHK * NH, 256, CB_SMEM, sB>>>(b, s * SLCHK);
        }
        scan_kernel<<<NH, 512, 0, sB>>>(b);
        yoff_kernel<<<NCH * NH, 256, YOFF_SMEM, sB>>>(b, Dv, z_bias);
        gemm_mma<<<g2grid, 256, GEMM_SMEM, sB>>>(out, p_yS, p_WoutS, 1024, 1024, b * LSEQ);
    }
    cudaEventRecord(evB, sB);

    // ---- join ----
    cudaStreamWaitEvent(0, evB, 0);
}